// round 1
// baseline (speedup 1.0000x reference)
#include <cuda_runtime.h>
#include <cstdint>
#include <cstddef>

// Problem constants (fixed shapes)
static constexpr int NTOK  = 8192;   // N*T*S = 2*16*256
static constexpr int DMODEL = 1024;
static constexpr int QKVD  = 3072;
static constexpr int HEADS = 8;      // per branch
static constexpr int DH    = 64;
static constexpr float SCALE = 0.125f;   // (1024/16)^-0.5

// Scratch (allocation-free: device globals)
__device__ float g_qkv[(size_t)NTOK * QKVD];   // 96 MB
__device__ float g_att[(size_t)NTOK * DMODEL]; // 32 MB, [spatial | temporal] concat

// ---------------------------------------------------------------------------
// SGEMM: C[M,N] = A[M,K] @ B[K,N] (+bias). M%128==0, N%128==0, K%8==0.
// 128x128 tile, BK=8, 256 threads, 8x8 microtile.
// ---------------------------------------------------------------------------
__global__ __launch_bounds__(256) void sgemm_kernel(
    const float* __restrict__ A, const float* __restrict__ B,
    const float* __restrict__ bias, float* __restrict__ C,
    int M, int N, int K)
{
    __shared__ float As[8][128];   // transposed A tile: As[k][m]
    __shared__ float Bs[8][128];

    const int tid = threadIdx.x;
    const int tx = tid & 15;       // 0..15 -> 8 cols each
    const int ty = tid >> 4;       // 0..15 -> 8 rows each
    const int bm = blockIdx.y * 128;
    const int bn = blockIdx.x * 128;

    // A tile load mapping: 128 rows x 8 cols = 1024 floats, float4 per thread
    const int arow = tid >> 1;           // 0..127
    const int acol = (tid & 1) * 4;      // 0 or 4
    // B tile: 8 rows x 128 cols
    const int brow = tid >> 5;           // 0..7
    const int bcol = (tid & 31) * 4;

    float acc[8][8];
    #pragma unroll
    for (int i = 0; i < 8; i++)
        #pragma unroll
        for (int j = 0; j < 8; j++) acc[i][j] = 0.f;

    const float* Ap = A + (size_t)(bm + arow) * K + acol;
    const float* Bp = B + (size_t)brow * N + bn + bcol;

    for (int k0 = 0; k0 < K; k0 += 8) {
        float4 av = *(const float4*)(Ap + k0);
        As[acol + 0][arow] = av.x;
        As[acol + 1][arow] = av.y;
        As[acol + 2][arow] = av.z;
        As[acol + 3][arow] = av.w;
        *(float4*)&Bs[brow][bcol] = *(const float4*)(Bp + (size_t)k0 * N);
        __syncthreads();

        #pragma unroll
        for (int kk = 0; kk < 8; kk++) {
            float ar[8], br[8];
            *(float4*)&ar[0] = *(const float4*)&As[kk][ty * 8];
            *(float4*)&ar[4] = *(const float4*)&As[kk][ty * 8 + 4];
            *(float4*)&br[0] = *(const float4*)&Bs[kk][tx * 8];
            *(float4*)&br[4] = *(const float4*)&Bs[kk][tx * 8 + 4];
            #pragma unroll
            for (int i = 0; i < 8; i++)
                #pragma unroll
                for (int j = 0; j < 8; j++)
                    acc[i][j] = fmaf(ar[i], br[j], acc[i][j]);
        }
        __syncthreads();
    }

    #pragma unroll
    for (int i = 0; i < 8; i++) {
        const int row = bm + ty * 8 + i;
        #pragma unroll
        for (int j = 0; j < 8; j += 4) {
            const int col = bn + tx * 8 + j;
            float4 v = make_float4(acc[i][j], acc[i][j + 1], acc[i][j + 2], acc[i][j + 3]);
            if (bias) {
                v.x += bias[col + 0];
                v.y += bias[col + 1];
                v.z += bias[col + 2];
                v.w += bias[col + 3];
            }
            *(float4*)(C + (size_t)row * N + col) = v;
        }
    }
}

// ---------------------------------------------------------------------------
// Spatial attention: one block per (n*T + t, head). 256 keys, 256 queries,
// head_dim 64. Whole K,V staged in smem; queries processed in chunks of 64.
// ---------------------------------------------------------------------------
struct SpatialSmem {
    float Kt[64][256];   // K transposed: Kt[d][key]
    float Vs[256][68];   // V padded rows (bank-conflict relief on stores)
    float Qt[64][64];    // Q chunk transposed: Qt[d][q_local]
    float Ps[64][256];   // scores / probs for the chunk
};

__global__ __launch_bounds__(256) void spatial_attn_kernel(
    const float* __restrict__ qkv, float* __restrict__ att)
{
    extern __shared__ char smem_raw[];
    SpatialSmem& sm = *reinterpret_cast<SpatialSmem*>(smem_raw);

    const int tid = threadIdx.x;
    const int h  = blockIdx.x & 7;
    const int nt = blockIdx.x >> 3;            // 0..31
    const size_t base = (size_t)nt * 256 * QKVD;
    const int qoff = h * DH;
    const int koff = 1024 + h * DH;
    const int voff = 2048 + h * DH;

    // Stage K (transposed) and V for all 256 keys
    {
        const int k = tid;
        const float* kp = qkv + base + (size_t)k * QKVD + koff;
        const float* vp = qkv + base + (size_t)k * QKVD + voff;
        #pragma unroll
        for (int d = 0; d < 64; d += 4) {
            float4 kv = *(const float4*)(kp + d);
            sm.Kt[d + 0][k] = kv.x;
            sm.Kt[d + 1][k] = kv.y;
            sm.Kt[d + 2][k] = kv.z;
            sm.Kt[d + 3][k] = kv.w;
            *(float4*)&sm.Vs[k][d] = *(const float4*)(vp + d);
        }
    }
    __syncthreads();

    for (int c = 0; c < 4; c++) {
        // Load Q chunk (64 queries) transposed
        {
            const int q  = tid >> 2;               // 0..63
            const int dg = (tid & 3) * 16;
            const float* qp = qkv + base + (size_t)(c * 64 + q) * QKVD + qoff + dg;
            #pragma unroll
            for (int d = 0; d < 16; d += 4) {
                float4 v = *(const float4*)(qp + d);
                sm.Qt[dg + d + 0][q] = v.x;
                sm.Qt[dg + d + 1][q] = v.y;
                sm.Qt[dg + d + 2][q] = v.z;
                sm.Qt[dg + d + 3][q] = v.w;
            }
        }
        __syncthreads();

        // Scores: S[64][256] = Qchunk @ K^T, register-tiled 8x8
        {
            const int ty = tid >> 5;     // 0..7  -> 8 query rows
            const int txw = tid & 31;    // 0..31 -> 8 key cols
            const int q0 = ty * 8;
            const int k0 = txw * 8;
            float acc[8][8];
            #pragma unroll
            for (int i = 0; i < 8; i++)
                #pragma unroll
                for (int j = 0; j < 8; j++) acc[i][j] = 0.f;

            #pragma unroll 8
            for (int d = 0; d < 64; d++) {
                float aq[8], bk[8];
                *(float4*)&aq[0] = *(const float4*)&sm.Qt[d][q0];
                *(float4*)&aq[4] = *(const float4*)&sm.Qt[d][q0 + 4];
                *(float4*)&bk[0] = *(const float4*)&sm.Kt[d][k0];
                *(float4*)&bk[4] = *(const float4*)&sm.Kt[d][k0 + 4];
                #pragma unroll
                for (int i = 0; i < 8; i++)
                    #pragma unroll
                    for (int j = 0; j < 8; j++)
                        acc[i][j] = fmaf(aq[i], bk[j], acc[i][j]);
            }
            #pragma unroll
            for (int i = 0; i < 8; i++)
                #pragma unroll
                for (int j = 0; j < 8; j += 4) {
                    float4 v = make_float4(acc[i][j] * SCALE, acc[i][j + 1] * SCALE,
                                           acc[i][j + 2] * SCALE, acc[i][j + 3] * SCALE);
                    *(float4*)&sm.Ps[q0 + i][k0 + j] = v;
                }
        }
        __syncthreads();

        // Softmax over keys: warp w handles 8 rows
        {
            const int w = tid >> 5, lane = tid & 31;
            for (int r8 = 0; r8 < 8; r8++) {
                const int r = w * 8 + r8;
                float v[8];
                float m = -1e30f;
                #pragma unroll
                for (int jj = 0; jj < 8; jj++) {
                    v[jj] = sm.Ps[r][lane + 32 * jj];
                    m = fmaxf(m, v[jj]);
                }
                #pragma unroll
                for (int o = 16; o > 0; o >>= 1) m = fmaxf(m, __shfl_xor_sync(0xffffffffu, m, o));
                float s = 0.f;
                #pragma unroll
                for (int jj = 0; jj < 8; jj++) { v[jj] = __expf(v[jj] - m); s += v[jj]; }
                #pragma unroll
                for (int o = 16; o > 0; o >>= 1) s += __shfl_xor_sync(0xffffffffu, s, o);
                const float inv = 1.f / s;
                #pragma unroll
                for (int jj = 0; jj < 8; jj++) sm.Ps[r][lane + 32 * jj] = v[jj] * inv;
            }
        }
        __syncthreads();

        // O[64][64] = P @ V, register-tiled 4x4, write straight to global
        {
            const int ty = tid >> 4;   // 0..15 -> 4 query rows
            const int txw = tid & 15;  // 0..15 -> 4 dims
            const int q0 = ty * 4;
            const int d0 = txw * 4;
            float acc[4][4];
            #pragma unroll
            for (int i = 0; i < 4; i++)
                #pragma unroll
                for (int j = 0; j < 4; j++) acc[i][j] = 0.f;

            for (int k = 0; k < 256; k += 4) {
                float p[4][4], vv[4][4];
                #pragma unroll
                for (int i = 0; i < 4; i++) {
                    float4 t = *(const float4*)&sm.Ps[q0 + i][k];
                    p[i][0] = t.x; p[i][1] = t.y; p[i][2] = t.z; p[i][3] = t.w;
                }
                #pragma unroll
                for (int kk = 0; kk < 4; kk++) {
                    float4 t = *(const float4*)&sm.Vs[k + kk][d0];
                    vv[kk][0] = t.x; vv[kk][1] = t.y; vv[kk][2] = t.z; vv[kk][3] = t.w;
                }
                #pragma unroll
                for (int i = 0; i < 4; i++)
                    #pragma unroll
                    for (int kk = 0; kk < 4; kk++)
                        #pragma unroll
                        for (int j = 0; j < 4; j++)
                            acc[i][j] = fmaf(p[i][kk], vv[kk][j], acc[i][j]);
            }
            #pragma unroll
            for (int i = 0; i < 4; i++) {
                const int row = nt * 256 + c * 64 + q0 + i;
                float4 v = make_float4(acc[i][0], acc[i][1], acc[i][2], acc[i][3]);
                *(float4*)(att + (size_t)row * DMODEL + h * DH + d0) = v;
            }
        }
        __syncthreads();
    }
}

// ---------------------------------------------------------------------------
// Temporal attention: one block per (n, s, head). 16 queries/keys, dim 64.
// ---------------------------------------------------------------------------
__global__ __launch_bounds__(128) void temporal_attn_kernel(
    const float* __restrict__ qkv, float* __restrict__ att)
{
    __shared__ float Qs[16][64], Ks[16][64], Vs[16][64];
    __shared__ float Ss[16][17];

    const int tid = threadIdx.x;       // 128
    const int h  = blockIdx.x & 7;
    const int ns = blockIdx.x >> 3;
    const int s  = ns & 255;
    const int n  = ns >> 8;
    const int qoff = 512  + h * DH;
    const int koff = 1536 + h * DH;
    const int voff = 2560 + h * DH;

    // Load Q/K/V [16][64]
    {
        const int r  = tid >> 3;            // 0..15 (time)
        const int dg = (tid & 7) * 8;       // 0..56
        const size_t tok = ((size_t)(n * 16 + r) * 256 + s) * QKVD;
        *(float4*)&Qs[r][dg]     = *(const float4*)(qkv + tok + qoff + dg);
        *(float4*)&Qs[r][dg + 4] = *(const float4*)(qkv + tok + qoff + dg + 4);
        *(float4*)&Ks[r][dg]     = *(const float4*)(qkv + tok + koff + dg);
        *(float4*)&Ks[r][dg + 4] = *(const float4*)(qkv + tok + koff + dg + 4);
        *(float4*)&Vs[r][dg]     = *(const float4*)(qkv + tok + voff + dg);
        *(float4*)&Vs[r][dg + 4] = *(const float4*)(qkv + tok + voff + dg + 4);
    }
    __syncthreads();

    // Scores: 2 per thread
    {
        const int q = tid >> 3;
        const int k = tid & 7;
        float s0 = 0.f, s1 = 0.f;
        #pragma unroll 16
        for (int d = 0; d < 64; d++) {
            const float qv = Qs[q][d];
            s0 = fmaf(qv, Ks[k][d], s0);
            s1 = fmaf(qv, Ks[k + 8][d], s1);
        }
        Ss[q][k]     = s0 * SCALE;
        Ss[q][k + 8] = s1 * SCALE;
    }
    __syncthreads();

    // Softmax per row (over keys)
    if (tid < 16) {
        float m = -1e30f;
        #pragma unroll
        for (int k = 0; k < 16; k++) m = fmaxf(m, Ss[tid][k]);
        float sum = 0.f;
        #pragma unroll
        for (int k = 0; k < 16; k++) {
            const float e = __expf(Ss[tid][k] - m);
            Ss[tid][k] = e;
            sum += e;
        }
        const float inv = 1.f / sum;
        #pragma unroll
        for (int k = 0; k < 16; k++) Ss[tid][k] *= inv;
    }
    __syncthreads();

    // AV + store
    {
        const int q  = tid >> 3;
        const int dg = (tid & 7) * 8;
        float o[8];
        #pragma unroll
        for (int j = 0; j < 8; j++) o[j] = 0.f;
        #pragma unroll
        for (int k = 0; k < 16; k++) {
            const float p = Ss[q][k];
            #pragma unroll
            for (int j = 0; j < 8; j++) o[j] = fmaf(p, Vs[k][dg + j], o[j]);
        }
        const size_t row = (size_t)(n * 16 + q) * 256 + s;
        *(float4*)(att + row * DMODEL + 512 + h * DH + dg)     = make_float4(o[0], o[1], o[2], o[3]);
        *(float4*)(att + row * DMODEL + 512 + h * DH + dg + 4) = make_float4(o[4], o[5], o[6], o[7]);
    }
}

// ---------------------------------------------------------------------------
extern "C" void kernel_launch(void* const* d_in, const int* in_sizes, int n_in,
                              void* d_out, int out_size)
{
    const float* x     = (const float*)d_in[0];
    const float* Wqkv  = (const float*)d_in[1];
    const float* Wproj = (const float*)d_in[2];
    const float* bproj = (const float*)d_in[3];
    float* out = (float*)d_out;

    float *qkv, *att;
    cudaGetSymbolAddress((void**)&qkv, g_qkv);
    cudaGetSymbolAddress((void**)&att, g_att);

    cudaFuncSetAttribute(spatial_attn_kernel,
                         cudaFuncAttributeMaxDynamicSharedMemorySize,
                         (int)sizeof(SpatialSmem));

    // 1) QKV GEMM: [8192,1024] @ [1024,3072]
    {
        dim3 grid(QKVD / 128, NTOK / 128);
        sgemm_kernel<<<grid, 256>>>(x, Wqkv, nullptr, qkv, NTOK, QKVD, DMODEL);
    }
    // 2) Spatial attention (writes att cols [0,512))
    spatial_attn_kernel<<<256, 256, sizeof(SpatialSmem)>>>(qkv, att);
    // 3) Temporal attention (writes att cols [512,1024))
    temporal_attn_kernel<<<4096, 128>>>(qkv, att);
    // 4) Output projection with bias
    {
        dim3 grid(DMODEL / 128, NTOK / 128);
        sgemm_kernel<<<grid, 256>>>(att, Wproj, bproj, out, NTOK, DMODEL, DMODEL);
    }
}

// round 4
// speedup vs baseline: 1.8967x; 1.8967x over previous
#include <cuda_runtime.h>
#include <cuda_bf16.h>
#include <cstdint>
#include <cstddef>

// ---------------- constants ----------------
static constexpr int NTOK   = 8192;   // N*T*S
static constexpr int DMODEL = 1024;
static constexpr int QKVD   = 3072;
static constexpr int DH     = 64;
static constexpr float SCALE = 0.125f;
static constexpr int KS = 3072;       // split-K: 3 * 1024

// ---------------- scratch (device globals, allocation-free) ----------------
__device__ float g_qkv[(size_t)NTOK * QKVD];            // 96 MB fp32
__device__ float g_att[(size_t)NTOK * DMODEL];          // 32 MB fp32
__device__ __nv_bfloat16 g_act2[(size_t)NTOK * KS];     // 48 MB bf16 split acts
__device__ __nv_bfloat16 g_w2qkv[(size_t)QKVD * KS];    // 18 MB
__device__ __nv_bfloat16 g_w2proj[(size_t)DMODEL * KS]; // 6 MB

// ---------------- PTX helpers (sm_80-level, no arch-feature suffix) --------
__device__ __forceinline__ uint32_t smem_u32(const void* p) {
    uint32_t a;
    asm("{ .reg .u64 t; cvta.to.shared.u64 t, %1; cvt.u32.u64 %0, t; }" : "=r"(a) : "l"(p));
    return a;
}
__device__ __forceinline__ void cp_async16(uint32_t s, const void* g) {
    asm volatile("cp.async.cg.shared.global [%0], [%1], 16;" :: "r"(s), "l"(g));
}
#define CP_COMMIT() asm volatile("cp.async.commit_group;" ::: "memory")
#define CP_WAIT(n)  asm volatile("cp.async.wait_group %0;" :: "n"(n) : "memory")

__device__ __forceinline__ void ldsm4(uint32_t (&r)[4], uint32_t addr) {
    asm volatile("ldmatrix.sync.aligned.m8n8.x4.shared.b16 {%0,%1,%2,%3}, [%4];"
                 : "=r"(r[0]), "=r"(r[1]), "=r"(r[2]), "=r"(r[3]) : "r"(addr));
}
__device__ __forceinline__ void mma_bf16(float (&c)[4], const uint32_t (&a)[4],
                                         uint32_t b0, uint32_t b1) {
    asm volatile(
        "mma.sync.aligned.m16n8k16.row.col.f32.bf16.bf16.f32 "
        "{%0,%1,%2,%3}, {%4,%5,%6,%7}, {%8,%9}, {%0,%1,%2,%3};"
        : "+f"(c[0]), "+f"(c[1]), "+f"(c[2]), "+f"(c[3])
        : "r"(a[0]), "r"(a[1]), "r"(a[2]), "r"(a[3]), "r"(b0), "r"(b1));
}

// ---------------- bf16x3 HMMA GEMM --------------------------------------
// C[M,N] fp32 = A2[M,KS] bf16 (K-major) x B2t[N,KS] bf16 (K-major)^T (+bias)
// BM=BN=128, BK=32; 8 warps (4 x 2), warp tile 32x64.
static constexpr int BM = 128, BN = 128, BK = 32;
static constexpr int ROWB = 80;            // smem row stride bytes (conflict-free)
static constexpr int TILEB = 128 * ROWB;   // 10240 per operand tile
static constexpr int BUFB = 2 * TILEB;     // A + B per stage

__global__ __launch_bounds__(256, 2) void gemm_mma_kernel(
    const __nv_bfloat16* __restrict__ A2, const __nv_bfloat16* __restrict__ B2t,
    const float* __restrict__ bias, float* __restrict__ C, int M, int N)
{
    __shared__ __align__(1024) uint8_t smem[2 * BUFB];  // 40 KB
    const uint32_t sb = smem_u32(smem);
    const int tid = threadIdx.x;
    const int wid = tid >> 5, lane = tid & 31;
    const int wm = wid >> 1, wn = wid & 1;
    const int bm = blockIdx.y * BM, bn = blockIdx.x * BN;

    float acc[2][8][4];
    #pragma unroll
    for (int i = 0; i < 2; i++)
        #pragma unroll
        for (int j = 0; j < 8; j++)
            #pragma unroll
            for (int q = 0; q < 4; q++) acc[i][j][q] = 0.f;

    auto load_tile = [&](int it, int buf) {
        const uint32_t s0 = sb + buf * BUFB;
        #pragma unroll
        for (int j = 0; j < 4; j++) {
            const int q = tid + j * 256;          // 0..1023
            const int isB = q >> 9;               // 0: A, 1: B
            const int r = (q & 511) >> 2;
            const int c = q & 3;
            const __nv_bfloat16* g = (isB ? B2t + (size_t)(bn + r) * KS
                                          : A2 + (size_t)(bm + r) * KS)
                                     + it * BK + c * 8;
            cp_async16(s0 + isB * TILEB + r * ROWB + c * 16, g);
        }
    };

    const int NIT = KS / BK;  // 96
    load_tile(0, 0);
    CP_COMMIT();

    int buf = 0;
    for (int it = 0; it < NIT; it++) {
        if (it + 1 < NIT) {
            load_tile(it + 1, buf ^ 1);
            CP_COMMIT();
            CP_WAIT(1);
        } else {
            CP_WAIT(0);
        }
        __syncthreads();

        const uint32_t abase = sb + buf * BUFB + wm * 32 * ROWB;
        const uint32_t bbase = sb + buf * BUFB + TILEB + wn * 64 * ROWB;
        const uint32_t arow = (lane & 15);
        const uint32_t acol = (lane >> 4) * 16;
        const uint32_t brow = (lane & 7) + ((lane & 16) >> 1);
        const uint32_t bcol = ((lane >> 3) & 1) * 16;

        #pragma unroll
        for (int ks = 0; ks < 2; ks++) {
            uint32_t a[2][4];
            #pragma unroll
            for (int mi = 0; mi < 2; mi++)
                ldsm4(a[mi], abase + (mi * 16 + arow) * ROWB + ks * 32 + acol);
            uint32_t b[4][4];
            #pragma unroll
            for (int nj = 0; nj < 4; nj++)
                ldsm4(b[nj], bbase + (nj * 16 + brow) * ROWB + ks * 32 + bcol);
            #pragma unroll
            for (int mi = 0; mi < 2; mi++)
                #pragma unroll
                for (int nj = 0; nj < 4; nj++) {
                    mma_bf16(acc[mi][nj * 2 + 0], a[mi], b[nj][0], b[nj][1]);
                    mma_bf16(acc[mi][nj * 2 + 1], a[mi], b[nj][2], b[nj][3]);
                }
        }
        __syncthreads();
        buf ^= 1;
    }

    // epilogue: c fragment -> gmem (float2 stores), optional bias
    const int g = lane >> 2, ti = lane & 3;
    #pragma unroll
    for (int mi = 0; mi < 2; mi++) {
        const int r0 = bm + wm * 32 + mi * 16 + g;
        #pragma unroll
        for (int nt = 0; nt < 8; nt++) {
            const int col = bn + wn * 64 + nt * 8 + 2 * ti;
            float2 v0 = make_float2(acc[mi][nt][0], acc[mi][nt][1]);
            float2 v1 = make_float2(acc[mi][nt][2], acc[mi][nt][3]);
            if (bias) {
                const float b0 = bias[col], b1 = bias[col + 1];
                v0.x += b0; v0.y += b1;
                v1.x += b0; v1.y += b1;
            }
            *(float2*)(C + (size_t)r0 * N + col)       = v0;
            *(float2*)(C + (size_t)(r0 + 8) * N + col) = v1;
        }
    }
}

// ---------------- split conversions ----------------
// acts: X[M,1024] fp32 -> X2[M,3072] bf16 : [hi | lo | hi]
__global__ __launch_bounds__(256) void split_act_kernel(
    const float* __restrict__ X, __nv_bfloat16* __restrict__ X2)
{
    const int i = blockIdx.x * 256 + threadIdx.x;
    const float v = X[i];
    const __nv_bfloat16 hi = __float2bfloat16(v);
    const __nv_bfloat16 lo = __float2bfloat16(v - __bfloat162float(hi));
    const int row = i >> 10, k = i & 1023;
    const size_t base = (size_t)row * KS + k;
    X2[base]        = hi;
    X2[base + 1024] = lo;
    X2[base + 2048] = hi;
}

// weights: W[1024,N] fp32 -> Wt[N,3072] bf16 (transposed) : [hi | hi | lo]
__global__ __launch_bounds__(256) void split_w_kernel(
    const float* __restrict__ W, __nv_bfloat16* __restrict__ Wt, int N)
{
    __shared__ float t[32][33];
    const int n0 = blockIdx.x * 32, k0 = blockIdx.y * 32;
    const int tx = threadIdx.x & 31, ty0 = threadIdx.x >> 5;
    #pragma unroll
    for (int i = 0; i < 4; i++) {
        const int ty = ty0 + i * 8;
        t[ty][tx] = W[(size_t)(k0 + ty) * N + n0 + tx];
    }
    __syncthreads();
    #pragma unroll
    for (int i = 0; i < 4; i++) {
        const int r = ty0 + i * 8;
        const float v = t[tx][r];
        const __nv_bfloat16 hi = __float2bfloat16(v);
        const __nv_bfloat16 lo = __float2bfloat16(v - __bfloat162float(hi));
        const size_t base = (size_t)(n0 + r) * KS + k0 + tx;
        Wt[base]        = hi;
        Wt[base + 1024] = hi;
        Wt[base + 2048] = lo;
    }
}

// ---------------- spatial attention (fp32) ----------------
struct SpatialSmem {
    float Kt[64][256];
    float Vs[256][68];
    float Qt[64][64];
    float Ps[64][256];
};

__global__ __launch_bounds__(256) void spatial_attn_kernel(
    const float* __restrict__ qkv, float* __restrict__ att)
{
    extern __shared__ char smem_raw[];
    SpatialSmem& sm = *reinterpret_cast<SpatialSmem*>(smem_raw);

    const int tid = threadIdx.x;
    const int h  = blockIdx.x & 7;
    const int nt = blockIdx.x >> 3;
    const size_t base = (size_t)nt * 256 * QKVD;
    const int qoff = h * DH;
    const int koff = 1024 + h * DH;
    const int voff = 2048 + h * DH;

    {
        const int k = tid;
        const float* kp = qkv + base + (size_t)k * QKVD + koff;
        const float* vp = qkv + base + (size_t)k * QKVD + voff;
        #pragma unroll
        for (int d = 0; d < 64; d += 4) {
            float4 kv = *(const float4*)(kp + d);
            sm.Kt[d + 0][k] = kv.x; sm.Kt[d + 1][k] = kv.y;
            sm.Kt[d + 2][k] = kv.z; sm.Kt[d + 3][k] = kv.w;
            *(float4*)&sm.Vs[k][d] = *(const float4*)(vp + d);
        }
    }
    __syncthreads();

    for (int c = 0; c < 4; c++) {
        {
            const int q  = tid >> 2;
            const int dg = (tid & 3) * 16;
            const float* qp = qkv + base + (size_t)(c * 64 + q) * QKVD + qoff + dg;
            #pragma unroll
            for (int d = 0; d < 16; d += 4) {
                float4 v = *(const float4*)(qp + d);
                sm.Qt[dg + d + 0][q] = v.x; sm.Qt[dg + d + 1][q] = v.y;
                sm.Qt[dg + d + 2][q] = v.z; sm.Qt[dg + d + 3][q] = v.w;
            }
        }
        __syncthreads();

        {
            const int ty = tid >> 5, txw = tid & 31;
            const int q0 = ty * 8, k0 = txw * 8;
            float acc[8][8];
            #pragma unroll
            for (int i = 0; i < 8; i++)
                #pragma unroll
                for (int j = 0; j < 8; j++) acc[i][j] = 0.f;
            #pragma unroll 8
            for (int d = 0; d < 64; d++) {
                float aq[8], bk[8];
                *(float4*)&aq[0] = *(const float4*)&sm.Qt[d][q0];
                *(float4*)&aq[4] = *(const float4*)&sm.Qt[d][q0 + 4];
                *(float4*)&bk[0] = *(const float4*)&sm.Kt[d][k0];
                *(float4*)&bk[4] = *(const float4*)&sm.Kt[d][k0 + 4];
                #pragma unroll
                for (int i = 0; i < 8; i++)
                    #pragma unroll
                    for (int j = 0; j < 8; j++)
                        acc[i][j] = fmaf(aq[i], bk[j], acc[i][j]);
            }
            #pragma unroll
            for (int i = 0; i < 8; i++)
                #pragma unroll
                for (int j = 0; j < 8; j += 4) {
                    float4 v = make_float4(acc[i][j] * SCALE, acc[i][j + 1] * SCALE,
                                           acc[i][j + 2] * SCALE, acc[i][j + 3] * SCALE);
                    *(float4*)&sm.Ps[q0 + i][k0 + j] = v;
                }
        }
        __syncthreads();

        {
            const int w = tid >> 5, lane = tid & 31;
            for (int r8 = 0; r8 < 8; r8++) {
                const int r = w * 8 + r8;
                float v[8];
                float m = -1e30f;
                #pragma unroll
                for (int jj = 0; jj < 8; jj++) {
                    v[jj] = sm.Ps[r][lane + 32 * jj];
                    m = fmaxf(m, v[jj]);
                }
                #pragma unroll
                for (int o = 16; o > 0; o >>= 1) m = fmaxf(m, __shfl_xor_sync(0xffffffffu, m, o));
                float s = 0.f;
                #pragma unroll
                for (int jj = 0; jj < 8; jj++) { v[jj] = __expf(v[jj] - m); s += v[jj]; }
                #pragma unroll
                for (int o = 16; o > 0; o >>= 1) s += __shfl_xor_sync(0xffffffffu, s, o);
                const float inv = 1.f / s;
                #pragma unroll
                for (int jj = 0; jj < 8; jj++) sm.Ps[r][lane + 32 * jj] = v[jj] * inv;
            }
        }
        __syncthreads();

        {
            const int ty = tid >> 4, txw = tid & 15;
            const int q0 = ty * 4, d0 = txw * 4;
            float acc[4][4];
            #pragma unroll
            for (int i = 0; i < 4; i++)
                #pragma unroll
                for (int j = 0; j < 4; j++) acc[i][j] = 0.f;
            for (int k = 0; k < 256; k += 4) {
                float p[4][4], vv[4][4];
                #pragma unroll
                for (int i = 0; i < 4; i++) {
                    float4 t = *(const float4*)&sm.Ps[q0 + i][k];
                    p[i][0] = t.x; p[i][1] = t.y; p[i][2] = t.z; p[i][3] = t.w;
                }
                #pragma unroll
                for (int kk = 0; kk < 4; kk++) {
                    float4 t = *(const float4*)&sm.Vs[k + kk][d0];
                    vv[kk][0] = t.x; vv[kk][1] = t.y; vv[kk][2] = t.z; vv[kk][3] = t.w;
                }
                #pragma unroll
                for (int i = 0; i < 4; i++)
                    #pragma unroll
                    for (int kk = 0; kk < 4; kk++)
                        #pragma unroll
                        for (int j = 0; j < 4; j++)
                            acc[i][j] = fmaf(p[i][kk], vv[kk][j], acc[i][j]);
            }
            #pragma unroll
            for (int i = 0; i < 4; i++) {
                const int row = nt * 256 + c * 64 + q0 + i;
                float4 v = make_float4(acc[i][0], acc[i][1], acc[i][2], acc[i][3]);
                *(float4*)(att + (size_t)row * DMODEL + h * DH + d0) = v;
            }
        }
        __syncthreads();
    }
}

// ---------------- temporal attention (fp32) ----------------
__global__ __launch_bounds__(128) void temporal_attn_kernel(
    const float* __restrict__ qkv, float* __restrict__ att)
{
    __shared__ float Qs[16][64], Ks2[16][64], Vs[16][64];
    __shared__ float Ss[16][17];

    const int tid = threadIdx.x;
    const int h  = blockIdx.x & 7;
    const int ns = blockIdx.x >> 3;
    const int s  = ns & 255;
    const int n  = ns >> 8;
    const int qoff = 512  + h * DH;
    const int koff = 1536 + h * DH;
    const int voff = 2560 + h * DH;

    {
        const int r  = tid >> 3;
        const int dg = (tid & 7) * 8;
        const size_t tok = ((size_t)(n * 16 + r) * 256 + s) * QKVD;
        *(float4*)&Qs[r][dg]      = *(const float4*)(qkv + tok + qoff + dg);
        *(float4*)&Qs[r][dg + 4]  = *(const float4*)(qkv + tok + qoff + dg + 4);
        *(float4*)&Ks2[r][dg]     = *(const float4*)(qkv + tok + koff + dg);
        *(float4*)&Ks2[r][dg + 4] = *(const float4*)(qkv + tok + koff + dg + 4);
        *(float4*)&Vs[r][dg]      = *(const float4*)(qkv + tok + voff + dg);
        *(float4*)&Vs[r][dg + 4]  = *(const float4*)(qkv + tok + voff + dg + 4);
    }
    __syncthreads();

    {
        const int q = tid >> 3;
        const int k = tid & 7;
        float s0 = 0.f, s1 = 0.f;
        #pragma unroll 16
        for (int d = 0; d < 64; d++) {
            const float qv = Qs[q][d];
            s0 = fmaf(qv, Ks2[k][d], s0);
            s1 = fmaf(qv, Ks2[k + 8][d], s1);
        }
        Ss[q][k]     = s0 * SCALE;
        Ss[q][k + 8] = s1 * SCALE;
    }
    __syncthreads();

    if (tid < 16) {
        float m = -1e30f;
        #pragma unroll
        for (int k = 0; k < 16; k++) m = fmaxf(m, Ss[tid][k]);
        float sum = 0.f;
        #pragma unroll
        for (int k = 0; k < 16; k++) {
            const float e = __expf(Ss[tid][k] - m);
            Ss[tid][k] = e;
            sum += e;
        }
        const float inv = 1.f / sum;
        #pragma unroll
        for (int k = 0; k < 16; k++) Ss[tid][k] *= inv;
    }
    __syncthreads();

    {
        const int q  = tid >> 3;
        const int dg = (tid & 7) * 8;
        float o[8];
        #pragma unroll
        for (int j = 0; j < 8; j++) o[j] = 0.f;
        #pragma unroll
        for (int k = 0; k < 16; k++) {
            const float p = Ss[q][k];
            #pragma unroll
            for (int j = 0; j < 8; j++) o[j] = fmaf(p, Vs[k][dg + j], o[j]);
        }
        const size_t row = (size_t)(n * 16 + q) * 256 + s;
        *(float4*)(att + row * DMODEL + 512 + h * DH + dg)     = make_float4(o[0], o[1], o[2], o[3]);
        *(float4*)(att + row * DMODEL + 512 + h * DH + dg + 4) = make_float4(o[4], o[5], o[6], o[7]);
    }
}

// ---------------- launch ----------------
extern "C" void kernel_launch(void* const* d_in, const int* in_sizes, int n_in,
                              void* d_out, int out_size)
{
    const float* x     = (const float*)d_in[0];
    const float* Wqkv  = (const float*)d_in[1];
    const float* Wproj = (const float*)d_in[2];
    const float* bproj = (const float*)d_in[3];
    float* out = (float*)d_out;

    float *qkv, *att;
    __nv_bfloat16 *act2, *w2qkv, *w2proj;
    cudaGetSymbolAddress((void**)&qkv, g_qkv);
    cudaGetSymbolAddress((void**)&att, g_att);
    cudaGetSymbolAddress((void**)&act2, g_act2);
    cudaGetSymbolAddress((void**)&w2qkv, g_w2qkv);
    cudaGetSymbolAddress((void**)&w2proj, g_w2proj);

    cudaFuncSetAttribute(spatial_attn_kernel,
                         cudaFuncAttributeMaxDynamicSharedMemorySize, (int)sizeof(SpatialSmem));

    // 1) splits
    split_act_kernel<<<NTOK * DMODEL / 256, 256>>>(x, act2);
    split_w_kernel<<<dim3(QKVD / 32, DMODEL / 32), 256>>>(Wqkv, w2qkv, QKVD);
    split_w_kernel<<<dim3(DMODEL / 32, DMODEL / 32), 256>>>(Wproj, w2proj, DMODEL);

    // 2) QKV GEMM: [8192,3072] = act2 x w2qkv^T (fp32 out)
    gemm_mma_kernel<<<dim3(QKVD / BN, NTOK / BM), 256>>>(
        act2, w2qkv, nullptr, qkv, NTOK, QKVD);

    // 3) attention
    spatial_attn_kernel<<<256, 256, sizeof(SpatialSmem)>>>(qkv, att);
    temporal_attn_kernel<<<4096, 128>>>(qkv, att);

    // 4) split att, proj GEMM with bias
    split_act_kernel<<<NTOK * DMODEL / 256, 256>>>(att, act2);
    gemm_mma_kernel<<<dim3(DMODEL / BN, NTOK / BM), 256>>>(
        act2, w2proj, bproj, out, NTOK, DMODEL);
}

// round 6
// speedup vs baseline: 2.0533x; 1.0825x over previous
#include <cuda_runtime.h>
#include <cuda_bf16.h>
#include <cstdint>
#include <cstddef>

// ---------------- constants ----------------
static constexpr int NTOK   = 8192;   // N*T*S
static constexpr int DMODEL = 1024;
static constexpr int QKVD   = 3072;
static constexpr int DH     = 64;
static constexpr float SCALE = 0.125f;
static constexpr int KS = 3072;       // split-K: 3 * 1024

// ---------------- scratch (device globals, allocation-free) ----------------
__device__ float g_qkv[(size_t)NTOK * QKVD];            // 96 MB fp32
__device__ float g_att[(size_t)NTOK * DMODEL];          // 32 MB fp32
__device__ __nv_bfloat16 g_act2[(size_t)NTOK * KS];     // 48 MB bf16 split acts
__device__ __nv_bfloat16 g_w2qkv[(size_t)QKVD * KS];    // 18 MB
__device__ __nv_bfloat16 g_w2proj[(size_t)DMODEL * KS]; // 6 MB

// ---------------- PTX helpers (sm_80-level, no arch-feature suffix) --------
__device__ __forceinline__ uint32_t smem_u32(const void* p) {
    uint32_t a;
    asm("{ .reg .u64 t; cvta.to.shared.u64 t, %1; cvt.u32.u64 %0, t; }" : "=r"(a) : "l"(p));
    return a;
}
__device__ __forceinline__ void cp_async16(uint32_t s, const void* g) {
    asm volatile("cp.async.cg.shared.global [%0], [%1], 16;" :: "r"(s), "l"(g));
}
#define CP_COMMIT() asm volatile("cp.async.commit_group;" ::: "memory")
#define CP_WAIT(n)  asm volatile("cp.async.wait_group %0;" :: "n"(n) : "memory")

__device__ __forceinline__ void ldsm4(uint32_t (&r)[4], uint32_t addr) {
    asm volatile("ldmatrix.sync.aligned.m8n8.x4.shared.b16 {%0,%1,%2,%3}, [%4];"
                 : "=r"(r[0]), "=r"(r[1]), "=r"(r[2]), "=r"(r[3]) : "r"(addr));
}
__device__ __forceinline__ void mma_bf16(float (&c)[4], const uint32_t (&a)[4],
                                         uint32_t b0, uint32_t b1) {
    asm volatile(
        "mma.sync.aligned.m16n8k16.row.col.f32.bf16.bf16.f32 "
        "{%0,%1,%2,%3}, {%4,%5,%6,%7}, {%8,%9}, {%0,%1,%2,%3};"
        : "+f"(c[0]), "+f"(c[1]), "+f"(c[2]), "+f"(c[3])
        : "r"(a[0]), "r"(a[1]), "r"(a[2]), "r"(a[3]), "r"(b0), "r"(b1));
}

// ---------------- bf16x3 HMMA GEMM --------------------------------------
// C[M,N] fp32 = A2[M,KS] bf16 (K-major) x B2t[N,KS] bf16 (K-major)^T (+bias)
// BM=BN=128, BK=64; 8 warps (4 x 2), warp tile 32x64.
// 3-stage cp.async pipeline, ONE __syncthreads per iteration.
static constexpr int BM = 128, BN = 128, BK = 64;
static constexpr int ROWB   = 144;             // 128B data + 16B pad (conflict-free)
static constexpr int TILEB  = 128 * ROWB;      // 18432 B per operand tile
static constexpr int STAGEB = 2 * TILEB;       // 36864 B per stage (A+B)
static constexpr int STAGES = 3;
static constexpr int GEMM_SMEM = STAGES * STAGEB;  // 110592 B

__global__ __launch_bounds__(256, 2) void gemm_mma_kernel(
    const __nv_bfloat16* __restrict__ A2, const __nv_bfloat16* __restrict__ B2t,
    const float* __restrict__ bias, float* __restrict__ C, int M, int N)
{
    extern __shared__ __align__(1024) uint8_t smem[];
    const uint32_t sb = smem_u32(smem);
    const int tid = threadIdx.x;
    const int wid = tid >> 5, lane = tid & 31;
    const int wm = wid >> 1, wn = wid & 1;
    const int bm = blockIdx.y * BM, bn = blockIdx.x * BN;

    float acc[2][8][4];
    #pragma unroll
    for (int i = 0; i < 2; i++)
        #pragma unroll
        for (int j = 0; j < 8; j++)
            #pragma unroll
            for (int q = 0; q < 4; q++) acc[i][j][q] = 0.f;

    // stage load: A 128 rows x 128B + B 128 rows x 128B = 2048 x 16B chunks
    auto load_tile = [&](int it, int st) {
        const uint32_t s0 = sb + st * STAGEB;
        #pragma unroll
        for (int j = 0; j < 8; j++) {
            const int q   = tid + j * 256;       // 0..2047
            const int isB = q >> 10;             // 0: A, 1: B
            const int r   = (q & 1023) >> 3;     // 0..127
            const int c   = q & 7;               // 16B chunk in 128B row
            const __nv_bfloat16* g = (isB ? B2t + (size_t)(bn + r) * KS
                                          : A2 + (size_t)(bm + r) * KS)
                                     + it * BK + c * 8;
            cp_async16(s0 + isB * TILEB + r * ROWB + c * 16, g);
        }
    };

    const int NIT = KS / BK;  // 48
    load_tile(0, 0);
    CP_COMMIT();
    load_tile(1, 1);
    CP_COMMIT();

    const uint32_t arow = (lane & 15);
    const uint32_t acol = (lane >> 4) * 16;
    const uint32_t brow = (lane & 7) + ((lane & 16) >> 1);
    const uint32_t bcol = ((lane >> 3) & 1) * 16;

    int st = 0;
    for (int it = 0; it < NIT; it++) {
        CP_WAIT(1);            // stage `it` resident
        __syncthreads();       // all warps done reading stage (it-1)%3

        // prefetch stage it+2 into buffer (it+2)%3 == (it-1)%3 (safe after barrier)
        if (it + 2 < NIT) {
            int st2 = st + 2; if (st2 >= STAGES) st2 -= STAGES;
            load_tile(it + 2, st2);
        }
        CP_COMMIT();

        const uint32_t sbase = sb + st * STAGEB;
        const uint32_t abase = sbase + wm * 32 * ROWB;
        const uint32_t bbase = sbase + TILEB + wn * 64 * ROWB;

        #pragma unroll
        for (int ks = 0; ks < 4; ks++) {
            uint32_t a[2][4];
            #pragma unroll
            for (int mi = 0; mi < 2; mi++)
                ldsm4(a[mi], abase + (mi * 16 + arow) * ROWB + ks * 32 + acol);
            uint32_t b[4][4];
            #pragma unroll
            for (int nj = 0; nj < 4; nj++)
                ldsm4(b[nj], bbase + (nj * 16 + brow) * ROWB + ks * 32 + bcol);
            #pragma unroll
            for (int mi = 0; mi < 2; mi++)
                #pragma unroll
                for (int nj = 0; nj < 4; nj++) {
                    mma_bf16(acc[mi][nj * 2 + 0], a[mi], b[nj][0], b[nj][1]);
                    mma_bf16(acc[mi][nj * 2 + 1], a[mi], b[nj][2], b[nj][3]);
                }
        }
        if (++st >= STAGES) st = 0;
    }

    // epilogue: c fragment -> gmem (float2 stores), optional bias
    const int g = lane >> 2, ti = lane & 3;
    #pragma unroll
    for (int mi = 0; mi < 2; mi++) {
        const int r0 = bm + wm * 32 + mi * 16 + g;
        #pragma unroll
        for (int nt = 0; nt < 8; nt++) {
            const int col = bn + wn * 64 + nt * 8 + 2 * ti;
            float2 v0 = make_float2(acc[mi][nt][0], acc[mi][nt][1]);
            float2 v1 = make_float2(acc[mi][nt][2], acc[mi][nt][3]);
            if (bias) {
                const float b0 = bias[col], b1 = bias[col + 1];
                v0.x += b0; v0.y += b1;
                v1.x += b0; v1.y += b1;
            }
            *(float2*)(C + (size_t)r0 * N + col)       = v0;
            *(float2*)(C + (size_t)(r0 + 8) * N + col) = v1;
        }
    }
}

// ---------------- split conversions ----------------
// acts: X[M,1024] fp32 -> X2[M,3072] bf16 : [hi | lo | hi]
__global__ __launch_bounds__(256) void split_act_kernel(
    const float* __restrict__ X, __nv_bfloat16* __restrict__ X2)
{
    const int i = blockIdx.x * 256 + threadIdx.x;
    const float v = X[i];
    const __nv_bfloat16 hi = __float2bfloat16(v);
    const __nv_bfloat16 lo = __float2bfloat16(v - __bfloat162float(hi));
    const int row = i >> 10, k = i & 1023;
    const size_t base = (size_t)row * KS + k;
    X2[base]        = hi;
    X2[base + 1024] = lo;
    X2[base + 2048] = hi;
}

// weights: W[1024,N] fp32 -> Wt[N,3072] bf16 (transposed) : [hi | hi | lo]
__global__ __launch_bounds__(256) void split_w_kernel(
    const float* __restrict__ W, __nv_bfloat16* __restrict__ Wt, int N)
{
    __shared__ float t[32][33];
    const int n0 = blockIdx.x * 32, k0 = blockIdx.y * 32;
    const int tx = threadIdx.x & 31, ty0 = threadIdx.x >> 5;
    #pragma unroll
    for (int i = 0; i < 4; i++) {
        const int ty = ty0 + i * 8;
        t[ty][tx] = W[(size_t)(k0 + ty) * N + n0 + tx];
    }
    __syncthreads();
    #pragma unroll
    for (int i = 0; i < 4; i++) {
        const int r = ty0 + i * 8;
        const float v = t[tx][r];
        const __nv_bfloat16 hi = __float2bfloat16(v);
        const __nv_bfloat16 lo = __float2bfloat16(v - __bfloat162float(hi));
        const size_t base = (size_t)(n0 + r) * KS + k0 + tx;
        Wt[base]        = hi;
        Wt[base + 1024] = hi;
        Wt[base + 2048] = lo;
    }
}

// ---------------- spatial attention (fp32) ----------------
struct SpatialSmem {
    float Kt[64][256];
    float Vs[256][68];
    float Qt[64][64];
    float Ps[64][256];
};

__global__ __launch_bounds__(256) void spatial_attn_kernel(
    const float* __restrict__ qkv, float* __restrict__ att)
{
    extern __shared__ char smem_raw[];
    SpatialSmem& sm = *reinterpret_cast<SpatialSmem*>(smem_raw);

    const int tid = threadIdx.x;
    const int h  = blockIdx.x & 7;
    const int nt = blockIdx.x >> 3;
    const size_t base = (size_t)nt * 256 * QKVD;
    const int qoff = h * DH;
    const int koff = 1024 + h * DH;
    const int voff = 2048 + h * DH;

    {
        const int k = tid;
        const float* kp = qkv + base + (size_t)k * QKVD + koff;
        const float* vp = qkv + base + (size_t)k * QKVD + voff;
        #pragma unroll
        for (int d = 0; d < 64; d += 4) {
            float4 kv = *(const float4*)(kp + d);
            sm.Kt[d + 0][k] = kv.x; sm.Kt[d + 1][k] = kv.y;
            sm.Kt[d + 2][k] = kv.z; sm.Kt[d + 3][k] = kv.w;
            *(float4*)&sm.Vs[k][d] = *(const float4*)(vp + d);
        }
    }
    __syncthreads();

    for (int c = 0; c < 4; c++) {
        {
            const int q  = tid >> 2;
            const int dg = (tid & 3) * 16;
            const float* qp = qkv + base + (size_t)(c * 64 + q) * QKVD + qoff + dg;
            #pragma unroll
            for (int d = 0; d < 16; d += 4) {
                float4 v = *(const float4*)(qp + d);
                sm.Qt[dg + d + 0][q] = v.x; sm.Qt[dg + d + 1][q] = v.y;
                sm.Qt[dg + d + 2][q] = v.z; sm.Qt[dg + d + 3][q] = v.w;
            }
        }
        __syncthreads();

        {
            const int ty = tid >> 5, txw = tid & 31;
            const int q0 = ty * 8, k0 = txw * 8;
            float acc[8][8];
            #pragma unroll
            for (int i = 0; i < 8; i++)
                #pragma unroll
                for (int j = 0; j < 8; j++) acc[i][j] = 0.f;
            #pragma unroll 8
            for (int d = 0; d < 64; d++) {
                float aq[8], bk[8];
                *(float4*)&aq[0] = *(const float4*)&sm.Qt[d][q0];
                *(float4*)&aq[4] = *(const float4*)&sm.Qt[d][q0 + 4];
                *(float4*)&bk[0] = *(const float4*)&sm.Kt[d][k0];
                *(float4*)&bk[4] = *(const float4*)&sm.Kt[d][k0 + 4];
                #pragma unroll
                for (int i = 0; i < 8; i++)
                    #pragma unroll
                    for (int j = 0; j < 8; j++)
                        acc[i][j] = fmaf(aq[i], bk[j], acc[i][j]);
            }
            #pragma unroll
            for (int i = 0; i < 8; i++)
                #pragma unroll
                for (int j = 0; j < 8; j += 4) {
                    float4 v = make_float4(acc[i][j] * SCALE, acc[i][j + 1] * SCALE,
                                           acc[i][j + 2] * SCALE, acc[i][j + 3] * SCALE);
                    *(float4*)&sm.Ps[q0 + i][k0 + j] = v;
                }
        }
        __syncthreads();

        {
            const int w = tid >> 5, lane = tid & 31;
            for (int r8 = 0; r8 < 8; r8++) {
                const int r = w * 8 + r8;
                float v[8];
                float m = -1e30f;
                #pragma unroll
                for (int jj = 0; jj < 8; jj++) {
                    v[jj] = sm.Ps[r][lane + 32 * jj];
                    m = fmaxf(m, v[jj]);
                }
                #pragma unroll
                for (int o = 16; o > 0; o >>= 1) m = fmaxf(m, __shfl_xor_sync(0xffffffffu, m, o));
                float s = 0.f;
                #pragma unroll
                for (int jj = 0; jj < 8; jj++) { v[jj] = __expf(v[jj] - m); s += v[jj]; }
                #pragma unroll
                for (int o = 16; o > 0; o >>= 1) s += __shfl_xor_sync(0xffffffffu, s, o);
                const float inv = 1.f / s;
                #pragma unroll
                for (int jj = 0; jj < 8; jj++) sm.Ps[r][lane + 32 * jj] = v[jj] * inv;
            }
        }
        __syncthreads();

        {
            const int ty = tid >> 4, txw = tid & 15;
            const int q0 = ty * 4, d0 = txw * 4;
            float acc[4][4];
            #pragma unroll
            for (int i = 0; i < 4; i++)
                #pragma unroll
                for (int j = 0; j < 4; j++) acc[i][j] = 0.f;
            for (int k = 0; k < 256; k += 4) {
                float p[4][4], vv[4][4];
                #pragma unroll
                for (int i = 0; i < 4; i++) {
                    float4 t = *(const float4*)&sm.Ps[q0 + i][k];
                    p[i][0] = t.x; p[i][1] = t.y; p[i][2] = t.z; p[i][3] = t.w;
                }
                #pragma unroll
                for (int kk = 0; kk < 4; kk++) {
                    float4 t = *(const float4*)&sm.Vs[k + kk][d0];
                    vv[kk][0] = t.x; vv[kk][1] = t.y; vv[kk][2] = t.z; vv[kk][3] = t.w;
                }
                #pragma unroll
                for (int i = 0; i < 4; i++)
                    #pragma unroll
                    for (int kk = 0; kk < 4; kk++)
                        #pragma unroll
                        for (int j = 0; j < 4; j++)
                            acc[i][j] = fmaf(p[i][kk], vv[kk][j], acc[i][j]);
            }
            #pragma unroll
            for (int i = 0; i < 4; i++) {
                const int row = nt * 256 + c * 64 + q0 + i;
                float4 v = make_float4(acc[i][0], acc[i][1], acc[i][2], acc[i][3]);
                *(float4*)(att + (size_t)row * DMODEL + h * DH + d0) = v;
            }
        }
        __syncthreads();
    }
}

// ---------------- temporal attention (fp32) ----------------
__global__ __launch_bounds__(128) void temporal_attn_kernel(
    const float* __restrict__ qkv, float* __restrict__ att)
{
    __shared__ float Qs[16][64], Ks2[16][64], Vs[16][64];
    __shared__ float Ss[16][17];

    const int tid = threadIdx.x;
    const int h  = blockIdx.x & 7;
    const int ns = blockIdx.x >> 3;
    const int s  = ns & 255;
    const int n  = ns >> 8;
    const int qoff = 512  + h * DH;
    const int koff = 1536 + h * DH;
    const int voff = 2560 + h * DH;

    {
        const int r  = tid >> 3;
        const int dg = (tid & 7) * 8;
        const size_t tok = ((size_t)(n * 16 + r) * 256 + s) * QKVD;
        *(float4*)&Qs[r][dg]      = *(const float4*)(qkv + tok + qoff + dg);
        *(float4*)&Qs[r][dg + 4]  = *(const float4*)(qkv + tok + qoff + dg + 4);
        *(float4*)&Ks2[r][dg]     = *(const float4*)(qkv + tok + koff + dg);
        *(float4*)&Ks2[r][dg + 4] = *(const float4*)(qkv + tok + koff + dg + 4);
        *(float4*)&Vs[r][dg]      = *(const float4*)(qkv + tok + voff + dg);
        *(float4*)&Vs[r][dg + 4]  = *(const float4*)(qkv + tok + voff + dg + 4);
    }
    __syncthreads();

    {
        const int q = tid >> 3;
        const int k = tid & 7;
        float s0 = 0.f, s1 = 0.f;
        #pragma unroll 16
        for (int d = 0; d < 64; d++) {
            const float qv = Qs[q][d];
            s0 = fmaf(qv, Ks2[k][d], s0);
            s1 = fmaf(qv, Ks2[k + 8][d], s1);
        }
        Ss[q][k]     = s0 * SCALE;
        Ss[q][k + 8] = s1 * SCALE;
    }
    __syncthreads();

    if (tid < 16) {
        float m = -1e30f;
        #pragma unroll
        for (int k = 0; k < 16; k++) m = fmaxf(m, Ss[tid][k]);
        float sum = 0.f;
        #pragma unroll
        for (int k = 0; k < 16; k++) {
            const float e = __expf(Ss[tid][k] - m);
            Ss[tid][k] = e;
            sum += e;
        }
        const float inv = 1.f / sum;
        #pragma unroll
        for (int k = 0; k < 16; k++) Ss[tid][k] *= inv;
    }
    __syncthreads();

    {
        const int q  = tid >> 3;
        const int dg = (tid & 7) * 8;
        float o[8];
        #pragma unroll
        for (int j = 0; j < 8; j++) o[j] = 0.f;
        #pragma unroll
        for (int k = 0; k < 16; k++) {
            const float p = Ss[q][k];
            #pragma unroll
            for (int j = 0; j < 8; j++) o[j] = fmaf(p, Vs[k][dg + j], o[j]);
        }
        const size_t row = (size_t)(n * 16 + q) * 256 + s;
        *(float4*)(att + row * DMODEL + 512 + h * DH + dg)     = make_float4(o[0], o[1], o[2], o[3]);
        *(float4*)(att + row * DMODEL + 512 + h * DH + dg + 4) = make_float4(o[4], o[5], o[6], o[7]);
    }
}

// ---------------- launch ----------------
extern "C" void kernel_launch(void* const* d_in, const int* in_sizes, int n_in,
                              void* d_out, int out_size)
{
    const float* x     = (const float*)d_in[0];
    const float* Wqkv  = (const float*)d_in[1];
    const float* Wproj = (const float*)d_in[2];
    const float* bproj = (const float*)d_in[3];
    float* out = (float*)d_out;

    float *qkv, *att;
    __nv_bfloat16 *act2, *w2qkv, *w2proj;
    cudaGetSymbolAddress((void**)&qkv, g_qkv);
    cudaGetSymbolAddress((void**)&att, g_att);
    cudaGetSymbolAddress((void**)&act2, g_act2);
    cudaGetSymbolAddress((void**)&w2qkv, g_w2qkv);
    cudaGetSymbolAddress((void**)&w2proj, g_w2proj);

    cudaFuncSetAttribute(spatial_attn_kernel,
                         cudaFuncAttributeMaxDynamicSharedMemorySize, (int)sizeof(SpatialSmem));
    cudaFuncSetAttribute(gemm_mma_kernel,
                         cudaFuncAttributeMaxDynamicSharedMemorySize, GEMM_SMEM);

    // 1) splits
    split_act_kernel<<<NTOK * DMODEL / 256, 256>>>(x, act2);
    split_w_kernel<<<dim3(QKVD / 32, DMODEL / 32), 256>>>(Wqkv, w2qkv, QKVD);
    split_w_kernel<<<dim3(DMODEL / 32, DMODEL / 32), 256>>>(Wproj, w2proj, DMODEL);

    // 2) QKV GEMM: [8192,3072] = act2 x w2qkv^T (fp32 out)
    gemm_mma_kernel<<<dim3(QKVD / BN, NTOK / BM), 256, GEMM_SMEM>>>(
        act2, w2qkv, nullptr, qkv, NTOK, QKVD);

    // 3) attention
    spatial_attn_kernel<<<256, 256, sizeof(SpatialSmem)>>>(qkv, att);
    temporal_attn_kernel<<<4096, 128>>>(qkv, att);

    // 4) split att, proj GEMM with bias
    split_act_kernel<<<NTOK * DMODEL / 256, 256>>>(att, act2);
    gemm_mma_kernel<<<dim3(DMODEL / BN, NTOK / BM), 256, GEMM_SMEM>>>(
        act2, w2proj, bproj, out, NTOK, DMODEL);
}

// round 7
// speedup vs baseline: 2.3348x; 1.1371x over previous
#include <cuda_runtime.h>
#include <cuda_bf16.h>
#include <cstdint>
#include <cstddef>

// ---------------- constants ----------------
static constexpr int NTOK   = 8192;   // N*T*S
static constexpr int DMODEL = 1024;
static constexpr int QKVD   = 3072;
static constexpr int DH     = 64;
static constexpr float SCALE = 0.125f;
static constexpr int KP     = 1024;   // K per plane (hi/lo separate)

// ---------------- scratch (device globals, allocation-free) ----------------
__device__ float g_qkv[(size_t)NTOK * QKVD];            // 96 MB fp32
__device__ float g_att[(size_t)NTOK * DMODEL];          // 32 MB fp32
__device__ __nv_bfloat16 g_acthi[(size_t)NTOK * KP];    // 16 MB
__device__ __nv_bfloat16 g_actlo[(size_t)NTOK * KP];    // 16 MB
__device__ __nv_bfloat16 g_wqhi[(size_t)QKVD * KP];     // 6 MB (transposed)
__device__ __nv_bfloat16 g_wqlo[(size_t)QKVD * KP];     // 6 MB
__device__ __nv_bfloat16 g_wphi[(size_t)DMODEL * KP];   // 2 MB
__device__ __nv_bfloat16 g_wplo[(size_t)DMODEL * KP];   // 2 MB

// ---------------- PTX helpers (sm_80-level) --------------------------------
__device__ __forceinline__ uint32_t smem_u32(const void* p) {
    uint32_t a;
    asm("{ .reg .u64 t; cvta.to.shared.u64 t, %1; cvt.u32.u64 %0, t; }" : "=r"(a) : "l"(p));
    return a;
}
__device__ __forceinline__ void cp_async16(uint32_t s, const void* g) {
    asm volatile("cp.async.cg.shared.global [%0], [%1], 16;" :: "r"(s), "l"(g));
}
#define CP_COMMIT() asm volatile("cp.async.commit_group;" ::: "memory")
#define CP_WAIT(n)  asm volatile("cp.async.wait_group %0;" :: "n"(n) : "memory")

__device__ __forceinline__ void ldsm4(uint32_t (&r)[4], uint32_t addr) {
    asm volatile("ldmatrix.sync.aligned.m8n8.x4.shared.b16 {%0,%1,%2,%3}, [%4];"
                 : "=r"(r[0]), "=r"(r[1]), "=r"(r[2]), "=r"(r[3]) : "r"(addr));
}
__device__ __forceinline__ void mma_bf16(float (&c)[4], const uint32_t (&a)[4],
                                         uint32_t b0, uint32_t b1) {
    asm volatile(
        "mma.sync.aligned.m16n8k16.row.col.f32.bf16.bf16.f32 "
        "{%0,%1,%2,%3}, {%4,%5,%6,%7}, {%8,%9}, {%0,%1,%2,%3};"
        : "+f"(c[0]), "+f"(c[1]), "+f"(c[2]), "+f"(c[3])
        : "r"(a[0]), "r"(a[1]), "r"(a[2]), "r"(a[3]), "r"(b0), "r"(b1));
}

// ---------------- bf16x3 HMMA GEMM, hi/lo plane form ----------------------
// C[M,N] fp32 = Ahi*Bhi + Alo*Bhi + Ahi*Blo (all K-major planes [rows][1024])
// BM=BN=128, BK=32; 8 warps (4m x 2n), warp tile 32x64.
// 3-stage cp.async pipeline, ONE __syncthreads per iteration.
// Smem tile: 128 rows x 64B, XOR swizzle (no pad): chunk' = chunk ^ ((row>>1)&3)
static constexpr int BM = 128, BN = 128, BK = 32;
static constexpr int TILE   = 128 * 64;        // 8192 B per operand tile
static constexpr int STAGEB = 4 * TILE;        // Ahi,Alo,Bhi,Blo = 32768 B
static constexpr int STAGES = 3;
static constexpr int GEMM_SMEM = STAGES * STAGEB;  // 98304 B

__device__ __forceinline__ uint32_t swz(uint32_t tbase, int row, int kc) {
    return tbase + row * 64 + ((kc ^ ((row >> 1) & 3)) << 4);
}

__global__ __launch_bounds__(256, 2) void gemm_mma_kernel(
    const __nv_bfloat16* __restrict__ Ahi, const __nv_bfloat16* __restrict__ Alo,
    const __nv_bfloat16* __restrict__ Bhi, const __nv_bfloat16* __restrict__ Blo,
    const float* __restrict__ bias, float* __restrict__ C, int M, int N)
{
    extern __shared__ __align__(1024) uint8_t smem[];
    const uint32_t sb = smem_u32(smem);
    const int tid = threadIdx.x;
    const int wid = tid >> 5, lane = tid & 31;
    const int wm = wid >> 1, wn = wid & 1;
    const int bm = blockIdx.y * BM, bn = blockIdx.x * BN;

    float acc[2][8][4];
    #pragma unroll
    for (int i = 0; i < 2; i++)
        #pragma unroll
        for (int j = 0; j < 8; j++)
            #pragma unroll
            for (int q = 0; q < 4; q++) acc[i][j][q] = 0.f;

    // stage load: 4 tiles x 128 rows x 64B = 2048 x 16B chunks; t = j>>1 const per j
    auto load_tile = [&](int it, int st) {
        const uint32_t s0 = sb + st * STAGEB;
        #pragma unroll
        for (int j = 0; j < 8; j++) {
            const int t = j >> 1;                      // 0:Ahi 1:Alo 2:Bhi 3:Blo
            const int r = (j & 1) * 64 + (tid >> 2);   // 0..127
            const int c = tid & 3;                     // 16B chunk in 64B row
            const __nv_bfloat16* pl = (t == 0) ? Ahi : (t == 1) ? Alo
                                    : (t == 2) ? Bhi : Blo;
            const int row0 = (t < 2) ? bm : bn;
            const __nv_bfloat16* g = pl + (size_t)(row0 + r) * KP + it * BK + c * 8;
            cp_async16(s0 + t * TILE + r * 64 + ((c ^ ((r >> 1) & 3)) << 4), g);
        }
    };

    const int NIT = KP / BK;  // 32
    load_tile(0, 0);
    CP_COMMIT();
    load_tile(1, 1);
    CP_COMMIT();

    const int arow  = lane & 15;
    const int ahalf = lane >> 4;
    const int brow  = (lane & 7) + ((lane & 16) >> 1);
    const int bhalf = (lane >> 3) & 1;

    int st = 0;
    for (int it = 0; it < NIT; it++) {
        CP_WAIT(1);            // stage `it` resident
        __syncthreads();       // all warps done reading stage (it-1)%3

        if (it + 2 < NIT) {
            int st2 = st + 2; if (st2 >= STAGES) st2 -= STAGES;
            load_tile(it + 2, st2);
        }
        CP_COMMIT();

        const uint32_t sbase = sb + st * STAGEB;
        const uint32_t Tahi = sbase;
        const uint32_t Talo = sbase + TILE;
        const uint32_t Tbhi = sbase + 2 * TILE;
        const uint32_t Tblo = sbase + 3 * TILE;

        #pragma unroll
        for (int ks = 0; ks < 2; ks++) {
            const int akc = ks * 2 + ahalf;
            const int bkc = ks * 2 + bhalf;

            uint32_t ah[2][4], al[2][4];
            #pragma unroll
            for (int mi = 0; mi < 2; mi++) {
                const int row = wm * 32 + mi * 16 + arow;
                ldsm4(ah[mi], swz(Tahi, row, akc));
                ldsm4(al[mi], swz(Talo, row, akc));
            }
            uint32_t bh[4][4];
            #pragma unroll
            for (int nj = 0; nj < 4; nj++) {
                const int row = wn * 64 + nj * 16 + brow;
                ldsm4(bh[nj], swz(Tbhi, row, bkc));
            }
            // pass 1: Ahi * Bhi
            #pragma unroll
            for (int mi = 0; mi < 2; mi++)
                #pragma unroll
                for (int nj = 0; nj < 4; nj++) {
                    mma_bf16(acc[mi][nj * 2 + 0], ah[mi], bh[nj][0], bh[nj][1]);
                    mma_bf16(acc[mi][nj * 2 + 1], ah[mi], bh[nj][2], bh[nj][3]);
                }
            // pass 2: Alo * Bhi
            #pragma unroll
            for (int mi = 0; mi < 2; mi++)
                #pragma unroll
                for (int nj = 0; nj < 4; nj++) {
                    mma_bf16(acc[mi][nj * 2 + 0], al[mi], bh[nj][0], bh[nj][1]);
                    mma_bf16(acc[mi][nj * 2 + 1], al[mi], bh[nj][2], bh[nj][3]);
                }
            // pass 3: Ahi * Blo
            uint32_t bl[4][4];
            #pragma unroll
            for (int nj = 0; nj < 4; nj++) {
                const int row = wn * 64 + nj * 16 + brow;
                ldsm4(bl[nj], swz(Tblo, row, bkc));
            }
            #pragma unroll
            for (int mi = 0; mi < 2; mi++)
                #pragma unroll
                for (int nj = 0; nj < 4; nj++) {
                    mma_bf16(acc[mi][nj * 2 + 0], ah[mi], bl[nj][0], bl[nj][1]);
                    mma_bf16(acc[mi][nj * 2 + 1], ah[mi], bl[nj][2], bl[nj][3]);
                }
        }
        if (++st >= STAGES) st = 0;
    }

    // epilogue: c fragment -> gmem (float2 stores), optional bias
    const int g = lane >> 2, ti = lane & 3;
    #pragma unroll
    for (int mi = 0; mi < 2; mi++) {
        const int r0 = bm + wm * 32 + mi * 16 + g;
        #pragma unroll
        for (int nt = 0; nt < 8; nt++) {
            const int col = bn + wn * 64 + nt * 8 + 2 * ti;
            float2 v0 = make_float2(acc[mi][nt][0], acc[mi][nt][1]);
            float2 v1 = make_float2(acc[mi][nt][2], acc[mi][nt][3]);
            if (bias) {
                const float b0 = bias[col], b1 = bias[col + 1];
                v0.x += b0; v0.y += b1;
                v1.x += b0; v1.y += b1;
            }
            *(float2*)(C + (size_t)r0 * N + col)       = v0;
            *(float2*)(C + (size_t)(r0 + 8) * N + col) = v1;
        }
    }
}

// ---------------- split conversions ----------------
// acts: X[M,1024] fp32 -> Hi[M,1024], Lo[M,1024] bf16
__global__ __launch_bounds__(256) void split_act_kernel(
    const float* __restrict__ X, __nv_bfloat16* __restrict__ Hi,
    __nv_bfloat16* __restrict__ Lo)
{
    const int i = blockIdx.x * 256 + threadIdx.x;
    const float v = X[i];
    const __nv_bfloat16 hi = __float2bfloat16(v);
    const __nv_bfloat16 lo = __float2bfloat16(v - __bfloat162float(hi));
    Hi[i] = hi;
    Lo[i] = lo;
}

// weights: W[1024,N] fp32 -> WhiT[N,1024], WloT[N,1024] bf16 (transposed)
__global__ __launch_bounds__(256) void split_w_kernel(
    const float* __restrict__ W, __nv_bfloat16* __restrict__ WhiT,
    __nv_bfloat16* __restrict__ WloT, int N)
{
    __shared__ float t[32][33];
    const int n0 = blockIdx.x * 32, k0 = blockIdx.y * 32;
    const int tx = threadIdx.x & 31, ty0 = threadIdx.x >> 5;
    #pragma unroll
    for (int i = 0; i < 4; i++) {
        const int ty = ty0 + i * 8;
        t[ty][tx] = W[(size_t)(k0 + ty) * N + n0 + tx];
    }
    __syncthreads();
    #pragma unroll
    for (int i = 0; i < 4; i++) {
        const int r = ty0 + i * 8;
        const float v = t[tx][r];
        const __nv_bfloat16 hi = __float2bfloat16(v);
        const __nv_bfloat16 lo = __float2bfloat16(v - __bfloat162float(hi));
        const size_t base = (size_t)(n0 + r) * KP + k0 + tx;
        WhiT[base] = hi;
        WloT[base] = lo;
    }
}

// ---------------- spatial attention (fp32) ----------------
struct SpatialSmem {
    float Kt[64][256];
    float Vs[256][68];
    float Qt[64][64];
    float Ps[64][256];
};

__global__ __launch_bounds__(256) void spatial_attn_kernel(
    const float* __restrict__ qkv, float* __restrict__ att)
{
    extern __shared__ char smem_raw[];
    SpatialSmem& sm = *reinterpret_cast<SpatialSmem*>(smem_raw);

    const int tid = threadIdx.x;
    const int h  = blockIdx.x & 7;
    const int nt = blockIdx.x >> 3;
    const size_t base = (size_t)nt * 256 * QKVD;
    const int qoff = h * DH;
    const int koff = 1024 + h * DH;
    const int voff = 2048 + h * DH;

    {
        const int k = tid;
        const float* kp = qkv + base + (size_t)k * QKVD + koff;
        const float* vp = qkv + base + (size_t)k * QKVD + voff;
        #pragma unroll
        for (int d = 0; d < 64; d += 4) {
            float4 kv = *(const float4*)(kp + d);
            sm.Kt[d + 0][k] = kv.x; sm.Kt[d + 1][k] = kv.y;
            sm.Kt[d + 2][k] = kv.z; sm.Kt[d + 3][k] = kv.w;
            *(float4*)&sm.Vs[k][d] = *(const float4*)(vp + d);
        }
    }
    __syncthreads();

    for (int c = 0; c < 4; c++) {
        {
            const int q  = tid >> 2;
            const int dg = (tid & 3) * 16;
            const float* qp = qkv + base + (size_t)(c * 64 + q) * QKVD + qoff + dg;
            #pragma unroll
            for (int d = 0; d < 16; d += 4) {
                float4 v = *(const float4*)(qp + d);
                sm.Qt[dg + d + 0][q] = v.x; sm.Qt[dg + d + 1][q] = v.y;
                sm.Qt[dg + d + 2][q] = v.z; sm.Qt[dg + d + 3][q] = v.w;
            }
        }
        __syncthreads();

        {
            const int ty = tid >> 5, txw = tid & 31;
            const int q0 = ty * 8, k0 = txw * 8;
            float acc[8][8];
            #pragma unroll
            for (int i = 0; i < 8; i++)
                #pragma unroll
                for (int j = 0; j < 8; j++) acc[i][j] = 0.f;
            #pragma unroll 8
            for (int d = 0; d < 64; d++) {
                float aq[8], bk[8];
                *(float4*)&aq[0] = *(const float4*)&sm.Qt[d][q0];
                *(float4*)&aq[4] = *(const float4*)&sm.Qt[d][q0 + 4];
                *(float4*)&bk[0] = *(const float4*)&sm.Kt[d][k0];
                *(float4*)&bk[4] = *(const float4*)&sm.Kt[d][k0 + 4];
                #pragma unroll
                for (int i = 0; i < 8; i++)
                    #pragma unroll
                    for (int j = 0; j < 8; j++)
                        acc[i][j] = fmaf(aq[i], bk[j], acc[i][j]);
            }
            #pragma unroll
            for (int i = 0; i < 8; i++)
                #pragma unroll
                for (int j = 0; j < 8; j += 4) {
                    float4 v = make_float4(acc[i][j] * SCALE, acc[i][j + 1] * SCALE,
                                           acc[i][j + 2] * SCALE, acc[i][j + 3] * SCALE);
                    *(float4*)&sm.Ps[q0 + i][k0 + j] = v;
                }
        }
        __syncthreads();

        {
            const int w = tid >> 5, lane = tid & 31;
            for (int r8 = 0; r8 < 8; r8++) {
                const int r = w * 8 + r8;
                float v[8];
                float m = -1e30f;
                #pragma unroll
                for (int jj = 0; jj < 8; jj++) {
                    v[jj] = sm.Ps[r][lane + 32 * jj];
                    m = fmaxf(m, v[jj]);
                }
                #pragma unroll
                for (int o = 16; o > 0; o >>= 1) m = fmaxf(m, __shfl_xor_sync(0xffffffffu, m, o));
                float s = 0.f;
                #pragma unroll
                for (int jj = 0; jj < 8; jj++) { v[jj] = __expf(v[jj] - m); s += v[jj]; }
                #pragma unroll
                for (int o = 16; o > 0; o >>= 1) s += __shfl_xor_sync(0xffffffffu, s, o);
                const float inv = 1.f / s;
                #pragma unroll
                for (int jj = 0; jj < 8; jj++) sm.Ps[r][lane + 32 * jj] = v[jj] * inv;
            }
        }
        __syncthreads();

        {
            const int ty = tid >> 4, txw = tid & 15;
            const int q0 = ty * 4, d0 = txw * 4;
            float acc[4][4];
            #pragma unroll
            for (int i = 0; i < 4; i++)
                #pragma unroll
                for (int j = 0; j < 4; j++) acc[i][j] = 0.f;
            for (int k = 0; k < 256; k += 4) {
                float p[4][4], vv[4][4];
                #pragma unroll
                for (int i = 0; i < 4; i++) {
                    float4 t = *(const float4*)&sm.Ps[q0 + i][k];
                    p[i][0] = t.x; p[i][1] = t.y; p[i][2] = t.z; p[i][3] = t.w;
                }
                #pragma unroll
                for (int kk = 0; kk < 4; kk++) {
                    float4 t = *(const float4*)&sm.Vs[k + kk][d0];
                    vv[kk][0] = t.x; vv[kk][1] = t.y; vv[kk][2] = t.z; vv[kk][3] = t.w;
                }
                #pragma unroll
                for (int i = 0; i < 4; i++)
                    #pragma unroll
                    for (int kk = 0; kk < 4; kk++)
                        #pragma unroll
                        for (int j = 0; j < 4; j++)
                            acc[i][j] = fmaf(p[i][kk], vv[kk][j], acc[i][j]);
            }
            #pragma unroll
            for (int i = 0; i < 4; i++) {
                const int row = nt * 256 + c * 64 + q0 + i;
                float4 v = make_float4(acc[i][0], acc[i][1], acc[i][2], acc[i][3]);
                *(float4*)(att + (size_t)row * DMODEL + h * DH + d0) = v;
            }
        }
        __syncthreads();
    }
}

// ---------------- temporal attention (fp32) ----------------
__global__ __launch_bounds__(128) void temporal_attn_kernel(
    const float* __restrict__ qkv, float* __restrict__ att)
{
    __shared__ float Qs[16][64], Ks2[16][64], Vs[16][64];
    __shared__ float Ss[16][17];

    const int tid = threadIdx.x;
    const int h  = blockIdx.x & 7;
    const int ns = blockIdx.x >> 3;
    const int s  = ns & 255;
    const int n  = ns >> 8;
    const int qoff = 512  + h * DH;
    const int koff = 1536 + h * DH;
    const int voff = 2560 + h * DH;

    {
        const int r  = tid >> 3;
        const int dg = (tid & 7) * 8;
        const size_t tok = ((size_t)(n * 16 + r) * 256 + s) * QKVD;
        *(float4*)&Qs[r][dg]      = *(const float4*)(qkv + tok + qoff + dg);
        *(float4*)&Qs[r][dg + 4]  = *(const float4*)(qkv + tok + qoff + dg + 4);
        *(float4*)&Ks2[r][dg]     = *(const float4*)(qkv + tok + koff + dg);
        *(float4*)&Ks2[r][dg + 4] = *(const float4*)(qkv + tok + koff + dg + 4);
        *(float4*)&Vs[r][dg]      = *(const float4*)(qkv + tok + voff + dg);
        *(float4*)&Vs[r][dg + 4]  = *(const float4*)(qkv + tok + voff + dg + 4);
    }
    __syncthreads();

    {
        const int q = tid >> 3;
        const int k = tid & 7;
        float s0 = 0.f, s1 = 0.f;
        #pragma unroll 16
        for (int d = 0; d < 64; d++) {
            const float qv = Qs[q][d];
            s0 = fmaf(qv, Ks2[k][d], s0);
            s1 = fmaf(qv, Ks2[k + 8][d], s1);
        }
        Ss[q][k]     = s0 * SCALE;
        Ss[q][k + 8] = s1 * SCALE;
    }
    __syncthreads();

    if (tid < 16) {
        float m = -1e30f;
        #pragma unroll
        for (int k = 0; k < 16; k++) m = fmaxf(m, Ss[tid][k]);
        float sum = 0.f;
        #pragma unroll
        for (int k = 0; k < 16; k++) {
            const float e = __expf(Ss[tid][k] - m);
            Ss[tid][k] = e;
            sum += e;
        }
        const float inv = 1.f / sum;
        #pragma unroll
        for (int k = 0; k < 16; k++) Ss[tid][k] *= inv;
    }
    __syncthreads();

    {
        const int q  = tid >> 3;
        const int dg = (tid & 7) * 8;
        float o[8];
        #pragma unroll
        for (int j = 0; j < 8; j++) o[j] = 0.f;
        #pragma unroll
        for (int k = 0; k < 16; k++) {
            const float p = Ss[q][k];
            #pragma unroll
            for (int j = 0; j < 8; j++) o[j] = fmaf(p, Vs[k][dg + j], o[j]);
        }
        const size_t row = (size_t)(n * 16 + q) * 256 + s;
        *(float4*)(att + row * DMODEL + 512 + h * DH + dg)     = make_float4(o[0], o[1], o[2], o[3]);
        *(float4*)(att + row * DMODEL + 512 + h * DH + dg + 4) = make_float4(o[4], o[5], o[6], o[7]);
    }
}

// ---------------- launch ----------------
extern "C" void kernel_launch(void* const* d_in, const int* in_sizes, int n_in,
                              void* d_out, int out_size)
{
    const float* x     = (const float*)d_in[0];
    const float* Wqkv  = (const float*)d_in[1];
    const float* Wproj = (const float*)d_in[2];
    const float* bproj = (const float*)d_in[3];
    float* out = (float*)d_out;

    float *qkv, *att;
    __nv_bfloat16 *acthi, *actlo, *wqhi, *wqlo, *wphi, *wplo;
    cudaGetSymbolAddress((void**)&qkv, g_qkv);
    cudaGetSymbolAddress((void**)&att, g_att);
    cudaGetSymbolAddress((void**)&acthi, g_acthi);
    cudaGetSymbolAddress((void**)&actlo, g_actlo);
    cudaGetSymbolAddress((void**)&wqhi, g_wqhi);
    cudaGetSymbolAddress((void**)&wqlo, g_wqlo);
    cudaGetSymbolAddress((void**)&wphi, g_wphi);
    cudaGetSymbolAddress((void**)&wplo, g_wplo);

    cudaFuncSetAttribute(spatial_attn_kernel,
                         cudaFuncAttributeMaxDynamicSharedMemorySize, (int)sizeof(SpatialSmem));
    cudaFuncSetAttribute(gemm_mma_kernel,
                         cudaFuncAttributeMaxDynamicSharedMemorySize, GEMM_SMEM);

    // 1) splits
    split_act_kernel<<<NTOK * DMODEL / 256, 256>>>(x, acthi, actlo);
    split_w_kernel<<<dim3(QKVD / 32, DMODEL / 32), 256>>>(Wqkv, wqhi, wqlo, QKVD);
    split_w_kernel<<<dim3(DMODEL / 32, DMODEL / 32), 256>>>(Wproj, wphi, wplo, DMODEL);

    // 2) QKV GEMM: [8192,3072] (fp32 out)
    gemm_mma_kernel<<<dim3(QKVD / BN, NTOK / BM), 256, GEMM_SMEM>>>(
        acthi, actlo, wqhi, wqlo, nullptr, qkv, NTOK, QKVD);

    // 3) attention
    spatial_attn_kernel<<<256, 256, sizeof(SpatialSmem)>>>(qkv, att);
    temporal_attn_kernel<<<4096, 128>>>(qkv, att);

    // 4) split att, proj GEMM with bias
    split_act_kernel<<<NTOK * DMODEL / 256, 256>>>(att, acthi, actlo);
    gemm_mma_kernel<<<dim3(DMODEL / BN, NTOK / BM), 256, GEMM_SMEM>>>(
        acthi, actlo, wphi, wplo, bproj, out, NTOK, DMODEL);
}

// round 17
// speedup vs baseline: 2.7342x; 1.1710x over previous
#include <cuda_runtime.h>
#include <cuda_bf16.h>
#include <cstdint>
#include <cstddef>

// ---------------- constants ----------------
static constexpr int NTOK   = 8192;   // N*T*S
static constexpr int DMODEL = 1024;
static constexpr int QKVD   = 3072;
static constexpr int DH     = 64;
static constexpr float SCALE = 0.125f;
static constexpr int KP     = 1024;   // K per plane (hi/lo separate)

// ---------------- scratch (device globals, allocation-free) ----------------
__device__ __nv_bfloat16 g_qkvhi[(size_t)NTOK * QKVD];  // 48 MB
__device__ __nv_bfloat16 g_qkvlo[(size_t)NTOK * QKVD];  // 48 MB
__device__ __nv_bfloat16 g_atthi[(size_t)NTOK * DMODEL];// 16 MB
__device__ __nv_bfloat16 g_attlo[(size_t)NTOK * DMODEL];// 16 MB
__device__ __nv_bfloat16 g_acthi[(size_t)NTOK * KP];    // 16 MB
__device__ __nv_bfloat16 g_actlo[(size_t)NTOK * KP];    // 16 MB
__device__ __nv_bfloat16 g_wqhi[(size_t)QKVD * KP];     // 6 MB (transposed)
__device__ __nv_bfloat16 g_wqlo[(size_t)QKVD * KP];     // 6 MB
__device__ __nv_bfloat16 g_wphi[(size_t)DMODEL * KP];   // 2 MB
__device__ __nv_bfloat16 g_wplo[(size_t)DMODEL * KP];   // 2 MB

// ---------------- PTX helpers (sm_80-level) --------------------------------
__device__ __forceinline__ uint32_t smem_u32(const void* p) {
    uint32_t a;
    asm("{ .reg .u64 t; cvta.to.shared.u64 t, %1; cvt.u32.u64 %0, t; }" : "=r"(a) : "l"(p));
    return a;
}
__device__ __forceinline__ void cp_async16(uint32_t s, const void* g) {
    asm volatile("cp.async.cg.shared.global [%0], [%1], 16;" :: "r"(s), "l"(g));
}
#define CP_COMMIT() asm volatile("cp.async.commit_group;" ::: "memory")
#define CP_WAIT(n)  asm volatile("cp.async.wait_group %0;" :: "n"(n) : "memory")

__device__ __forceinline__ void ldsm4(uint32_t (&r)[4], uint32_t addr) {
    asm volatile("ldmatrix.sync.aligned.m8n8.x4.shared.b16 {%0,%1,%2,%3}, [%4];"
                 : "=r"(r[0]), "=r"(r[1]), "=r"(r[2]), "=r"(r[3]) : "r"(addr));
}
__device__ __forceinline__ void ldsm4t(uint32_t (&r)[4], uint32_t addr) {
    asm volatile("ldmatrix.sync.aligned.m8n8.x4.trans.shared.b16 {%0,%1,%2,%3}, [%4];"
                 : "=r"(r[0]), "=r"(r[1]), "=r"(r[2]), "=r"(r[3]) : "r"(addr));
}
__device__ __forceinline__ void mma_bf16(float (&c)[4], const uint32_t (&a)[4],
                                         uint32_t b0, uint32_t b1) {
    asm volatile(
        "mma.sync.aligned.m16n8k16.row.col.f32.bf16.bf16.f32 "
        "{%0,%1,%2,%3}, {%4,%5,%6,%7}, {%8,%9}, {%0,%1,%2,%3};"
        : "+f"(c[0]), "+f"(c[1]), "+f"(c[2]), "+f"(c[3])
        : "r"(a[0]), "r"(a[1]), "r"(a[2]), "r"(a[3]), "r"(b0), "r"(b1));
}
__device__ __forceinline__ uint32_t packbf2(float x, float y) {
    __nv_bfloat162 v;
    v.x = __float2bfloat16(x);
    v.y = __float2bfloat16(y);
    return *reinterpret_cast<uint32_t*>(&v);
}

// ---------------- bf16x3 HMMA GEMM, hi/lo plane form ----------------------
// C = Ahi*Bhi + Alo*Bhi + Ahi*Blo (K-major planes [rows][1024]).
// Output either fp32 (+bias) or split bf16 hi/lo planes.
static constexpr int BM = 128, BN = 128, BK = 32;
static constexpr int TILE   = 128 * 64;
static constexpr int STAGEB = 4 * TILE;
static constexpr int STAGES = 3;
static constexpr int GEMM_SMEM = STAGES * STAGEB;  // 98304 B

__device__ __forceinline__ uint32_t swzg(uint32_t tbase, int row, int kc) {
    return tbase + row * 64 + ((kc ^ ((row >> 1) & 3)) << 4);
}

__global__ __launch_bounds__(256, 2) void gemm_mma_kernel(
    const __nv_bfloat16* __restrict__ Ahi, const __nv_bfloat16* __restrict__ Alo,
    const __nv_bfloat16* __restrict__ Bhi, const __nv_bfloat16* __restrict__ Blo,
    const float* __restrict__ bias, float* __restrict__ C,
    __nv_bfloat16* __restrict__ Chi, __nv_bfloat16* __restrict__ Clo,
    int M, int N)
{
    extern __shared__ __align__(1024) uint8_t smem[];
    const uint32_t sb = smem_u32(smem);
    const int tid = threadIdx.x;
    const int wid = tid >> 5, lane = tid & 31;
    const int wm = wid >> 1, wn = wid & 1;
    const int bm = blockIdx.y * BM, bn = blockIdx.x * BN;

    float acc[2][8][4];
    #pragma unroll
    for (int i = 0; i < 2; i++)
        #pragma unroll
        for (int j = 0; j < 8; j++)
            #pragma unroll
            for (int q = 0; q < 4; q++) acc[i][j][q] = 0.f;

    auto load_tile = [&](int it, int st) {
        const uint32_t s0 = sb + st * STAGEB;
        #pragma unroll
        for (int j = 0; j < 8; j++) {
            const int t = j >> 1;                      // 0:Ahi 1:Alo 2:Bhi 3:Blo
            const int r = (j & 1) * 64 + (tid >> 2);
            const int c = tid & 3;
            const __nv_bfloat16* pl = (t == 0) ? Ahi : (t == 1) ? Alo
                                    : (t == 2) ? Bhi : Blo;
            const int row0 = (t < 2) ? bm : bn;
            const __nv_bfloat16* g = pl + (size_t)(row0 + r) * KP + it * BK + c * 8;
            cp_async16(s0 + t * TILE + r * 64 + ((c ^ ((r >> 1) & 3)) << 4), g);
        }
    };

    const int NIT = KP / BK;  // 32
    load_tile(0, 0);
    CP_COMMIT();
    load_tile(1, 1);
    CP_COMMIT();

    const int arow  = lane & 15;
    const int ahalf = lane >> 4;
    const int brow  = (lane & 7) + ((lane & 16) >> 1);
    const int bhalf = (lane >> 3) & 1;

    int st = 0;
    for (int it = 0; it < NIT; it++) {
        CP_WAIT(1);
        __syncthreads();

        if (it + 2 < NIT) {
            int st2 = st + 2; if (st2 >= STAGES) st2 -= STAGES;
            load_tile(it + 2, st2);
        }
        CP_COMMIT();

        const uint32_t sbase = sb + st * STAGEB;
        const uint32_t Tahi = sbase;
        const uint32_t Talo = sbase + TILE;
        const uint32_t Tbhi = sbase + 2 * TILE;
        const uint32_t Tblo = sbase + 3 * TILE;

        #pragma unroll
        for (int ks = 0; ks < 2; ks++) {
            const int akc = ks * 2 + ahalf;
            const int bkc = ks * 2 + bhalf;

            uint32_t ah[2][4], al[2][4];
            #pragma unroll
            for (int mi = 0; mi < 2; mi++) {
                const int row = wm * 32 + mi * 16 + arow;
                ldsm4(ah[mi], swzg(Tahi, row, akc));
                ldsm4(al[mi], swzg(Talo, row, akc));
            }
            uint32_t bh[4][4];
            #pragma unroll
            for (int nj = 0; nj < 4; nj++) {
                const int row = wn * 64 + nj * 16 + brow;
                ldsm4(bh[nj], swzg(Tbhi, row, bkc));
            }
            #pragma unroll
            for (int mi = 0; mi < 2; mi++)
                #pragma unroll
                for (int nj = 0; nj < 4; nj++) {
                    mma_bf16(acc[mi][nj * 2 + 0], ah[mi], bh[nj][0], bh[nj][1]);
                    mma_bf16(acc[mi][nj * 2 + 1], ah[mi], bh[nj][2], bh[nj][3]);
                }
            #pragma unroll
            for (int mi = 0; mi < 2; mi++)
                #pragma unroll
                for (int nj = 0; nj < 4; nj++) {
                    mma_bf16(acc[mi][nj * 2 + 0], al[mi], bh[nj][0], bh[nj][1]);
                    mma_bf16(acc[mi][nj * 2 + 1], al[mi], bh[nj][2], bh[nj][3]);
                }
            uint32_t bl[4][4];
            #pragma unroll
            for (int nj = 0; nj < 4; nj++) {
                const int row = wn * 64 + nj * 16 + brow;
                ldsm4(bl[nj], swzg(Tblo, row, bkc));
            }
            #pragma unroll
            for (int mi = 0; mi < 2; mi++)
                #pragma unroll
                for (int nj = 0; nj < 4; nj++) {
                    mma_bf16(acc[mi][nj * 2 + 0], ah[mi], bl[nj][0], bl[nj][1]);
                    mma_bf16(acc[mi][nj * 2 + 1], ah[mi], bl[nj][2], bl[nj][3]);
                }
        }
        if (++st >= STAGES) st = 0;
    }

    const int g = lane >> 2, ti = lane & 3;
    if (Chi) {
        // split bf16 hi/lo output
        #pragma unroll
        for (int mi = 0; mi < 2; mi++) {
            const int r0 = bm + wm * 32 + mi * 16 + g;
            #pragma unroll
            for (int nt = 0; nt < 8; nt++) {
                const int col = bn + wn * 64 + nt * 8 + 2 * ti;
                #pragma unroll
                for (int half = 0; half < 2; half++) {
                    const float x = acc[mi][nt][half * 2 + 0];
                    const float y = acc[mi][nt][half * 2 + 1];
                    const size_t idx = (size_t)(r0 + half * 8) * N + col;
                    __nv_bfloat162 hv;
                    hv.x = __float2bfloat16(x);
                    hv.y = __float2bfloat16(y);
                    *(__nv_bfloat162*)(Chi + idx) = hv;
                    __nv_bfloat162 lv;
                    lv.x = __float2bfloat16(x - __bfloat162float(hv.x));
                    lv.y = __float2bfloat16(y - __bfloat162float(hv.y));
                    *(__nv_bfloat162*)(Clo + idx) = lv;
                }
            }
        }
    } else {
        #pragma unroll
        for (int mi = 0; mi < 2; mi++) {
            const int r0 = bm + wm * 32 + mi * 16 + g;
            #pragma unroll
            for (int nt = 0; nt < 8; nt++) {
                const int col = bn + wn * 64 + nt * 8 + 2 * ti;
                float2 v0 = make_float2(acc[mi][nt][0], acc[mi][nt][1]);
                float2 v1 = make_float2(acc[mi][nt][2], acc[mi][nt][3]);
                if (bias) {
                    const float b0 = bias[col], b1 = bias[col + 1];
                    v0.x += b0; v0.y += b1;
                    v1.x += b0; v1.y += b1;
                }
                *(float2*)(C + (size_t)r0 * N + col)       = v0;
                *(float2*)(C + (size_t)(r0 + 8) * N + col) = v1;
            }
        }
    }
}

// ---------------- split conversions ----------------
__global__ __launch_bounds__(256) void split_act_kernel(
    const float* __restrict__ X, __nv_bfloat16* __restrict__ Hi,
    __nv_bfloat16* __restrict__ Lo)
{
    const int i = blockIdx.x * 256 + threadIdx.x;
    const float v = X[i];
    const __nv_bfloat16 hi = __float2bfloat16(v);
    Hi[i] = hi;
    Lo[i] = __float2bfloat16(v - __bfloat162float(hi));
}

__global__ __launch_bounds__(256) void split_w_kernel(
    const float* __restrict__ W, __nv_bfloat16* __restrict__ WhiT,
    __nv_bfloat16* __restrict__ WloT, int N)
{
    __shared__ float t[32][33];
    const int n0 = blockIdx.x * 32, k0 = blockIdx.y * 32;
    const int tx = threadIdx.x & 31, ty0 = threadIdx.x >> 5;
    #pragma unroll
    for (int i = 0; i < 4; i++) {
        const int ty = ty0 + i * 8;
        t[ty][tx] = W[(size_t)(k0 + ty) * N + n0 + tx];
    }
    __syncthreads();
    #pragma unroll
    for (int i = 0; i < 4; i++) {
        const int r = ty0 + i * 8;
        const float v = t[tx][r];
        const __nv_bfloat16 hi = __float2bfloat16(v);
        const size_t base = (size_t)(n0 + r) * KP + k0 + tx;
        WhiT[base] = hi;
        WloT[base] = __float2bfloat16(v - __bfloat162float(hi));
    }
}

// ---------------- spatial attention: HMMA bf16x3 ----------------
// 1 block per (nt, h): Q,K,V [256,64]. Chunks of 64 queries.
static constexpr int SAT_K_HI = 0;
static constexpr int SAT_K_LO = 32768;
static constexpr int SAT_V_HI = 65536;
static constexpr int SAT_V_LO = 98304;
static constexpr int SAT_Q_HI = 131072;
static constexpr int SAT_Q_LO = 139264;
static constexpr int SAT_OSM  = 147456;               // float[64][68]
static constexpr int SAT_REDM = SAT_OSM + 64 * 68 * 4;
static constexpr int SAT_REDS = SAT_REDM + 512;
static constexpr int SAT_SMEM = SAT_REDS + 512;       // 165888

__device__ __forceinline__ uint32_t swza(uint32_t tbase, int row, int kc) {
    return tbase + row * 128 + ((kc ^ (row & 7)) << 4);
}

__global__ __launch_bounds__(256, 1) void spatial_attn_mma(
    const __nv_bfloat16* __restrict__ qhi, const __nv_bfloat16* __restrict__ qlo,
    __nv_bfloat16* __restrict__ athi, __nv_bfloat16* __restrict__ atlo)
{
    extern __shared__ __align__(1024) uint8_t sm8[];
    const uint32_t sb = smem_u32(sm8);
    const int tid = threadIdx.x, wid = tid >> 5, lane = tid & 31;
    const int h = blockIdx.x & 7, nt = blockIdx.x >> 3;
    const int wq = wid >> 1, wk = wid & 1;
    const int g = lane >> 2, t = lane & 3;

    const size_t tokbase = (size_t)nt * 256;
    const int qoff = h * DH, koff = 1024 + h * DH, voff = 2048 + h * DH;

    float* redm = (float*)(sm8 + SAT_REDM);
    float* reds = (float*)(sm8 + SAT_REDS);
    float* osm  = (float*)(sm8 + SAT_OSM);

    // ---- stage K,V hi/lo ----
    {
        const int row = tid;
        const size_t gk = (tokbase + row) * QKVD;
        #pragma unroll
        for (int c = 0; c < 8; c++) {
            const uint32_t d = (uint32_t)row * 128 + ((c ^ (row & 7)) << 4);
            cp_async16(sb + SAT_K_HI + d, qhi + gk + koff + c * 8);
            cp_async16(sb + SAT_K_LO + d, qlo + gk + koff + c * 8);
            cp_async16(sb + SAT_V_HI + d, qhi + gk + voff + c * 8);
            cp_async16(sb + SAT_V_LO + d, qlo + gk + voff + c * 8);
        }
    }
    auto loadQ = [&](int ch) {
        const int row = tid >> 2;
        const int c0 = (tid & 3) * 2;
        const size_t gq = (tokbase + ch * 64 + row) * QKVD + qoff;
        #pragma unroll
        for (int cc = 0; cc < 2; cc++) {
            const int c = c0 + cc;
            const uint32_t d = (uint32_t)row * 128 + ((c ^ (row & 7)) << 4);
            cp_async16(sb + SAT_Q_HI + d, qhi + gq + c * 8);
            cp_async16(sb + SAT_Q_LO + d, qlo + gq + c * 8);
        }
    };
    loadQ(0);
    CP_COMMIT(); CP_WAIT(0);
    __syncthreads();

    const int qrow  = wq * 16 + (lane & 15);
    const int ahalf = lane >> 4;
    const int brow_ = (lane & 7) + ((lane & 16) >> 1);
    const int bhalf = (lane >> 3) & 1;
    const int vrow_b = wk * 128 + ((lane >> 3) & 1) * 8 + (lane & 7);
    const int vchalf = lane >> 4;

    for (int ch = 0; ch < 4; ch++) {
        // ---- S = Q K^T (bf16x3) ----
        float s[16][4];
        #pragma unroll
        for (int i = 0; i < 16; i++)
            #pragma unroll
            for (int j = 0; j < 4; j++) s[i][j] = 0.f;

        #pragma unroll
        for (int kg = 0; kg < 4; kg++) {
            uint32_t aqh[4], aql[4];
            ldsm4(aqh, swza(sb + SAT_Q_HI, qrow, kg * 2 + ahalf));
            ldsm4(aql, swza(sb + SAT_Q_LO, qrow, kg * 2 + ahalf));
            #pragma unroll
            for (int t2 = 0; t2 < 8; t2++) {
                const int krow = wk * 128 + t2 * 16 + brow_;
                uint32_t bh[4], bl[4];
                ldsm4(bh, swza(sb + SAT_K_HI, krow, kg * 2 + bhalf));
                ldsm4(bl, swza(sb + SAT_K_LO, krow, kg * 2 + bhalf));
                mma_bf16(s[2 * t2 + 0], aqh, bh[0], bh[1]);
                mma_bf16(s[2 * t2 + 1], aqh, bh[2], bh[3]);
                mma_bf16(s[2 * t2 + 0], aql, bh[0], bh[1]);
                mma_bf16(s[2 * t2 + 1], aql, bh[2], bh[3]);
                mma_bf16(s[2 * t2 + 0], aqh, bl[0], bl[1]);
                mma_bf16(s[2 * t2 + 1], aqh, bl[2], bl[3]);
            }
        }

        // ---- softmax (registers; normalization deferred) ----
        float m0 = -1e30f, m1 = -1e30f;
        #pragma unroll
        for (int i = 0; i < 16; i++) {
            s[i][0] *= SCALE; s[i][1] *= SCALE; s[i][2] *= SCALE; s[i][3] *= SCALE;
            m0 = fmaxf(m0, fmaxf(s[i][0], s[i][1]));
            m1 = fmaxf(m1, fmaxf(s[i][2], s[i][3]));
        }
        m0 = fmaxf(m0, __shfl_xor_sync(0xffffffffu, m0, 1));
        m0 = fmaxf(m0, __shfl_xor_sync(0xffffffffu, m0, 2));
        m1 = fmaxf(m1, __shfl_xor_sync(0xffffffffu, m1, 1));
        m1 = fmaxf(m1, __shfl_xor_sync(0xffffffffu, m1, 2));
        if (t == 0) {
            redm[(wq * 16 + g) * 2 + wk]     = m0;
            redm[(wq * 16 + g + 8) * 2 + wk] = m1;
        }
        __syncthreads();
        m0 = fmaxf(redm[(wq * 16 + g) * 2],     redm[(wq * 16 + g) * 2 + 1]);
        m1 = fmaxf(redm[(wq * 16 + g + 8) * 2], redm[(wq * 16 + g + 8) * 2 + 1]);

        float sum0 = 0.f, sum1 = 0.f;
        #pragma unroll
        for (int i = 0; i < 16; i++) {
            s[i][0] = __expf(s[i][0] - m0); sum0 += s[i][0];
            s[i][1] = __expf(s[i][1] - m0); sum0 += s[i][1];
            s[i][2] = __expf(s[i][2] - m1); sum1 += s[i][2];
            s[i][3] = __expf(s[i][3] - m1); sum1 += s[i][3];
        }
        sum0 += __shfl_xor_sync(0xffffffffu, sum0, 1);
        sum0 += __shfl_xor_sync(0xffffffffu, sum0, 2);
        sum1 += __shfl_xor_sync(0xffffffffu, sum1, 1);
        sum1 += __shfl_xor_sync(0xffffffffu, sum1, 2);
        if (t == 0) {
            reds[(wq * 16 + g) * 2 + wk]     = sum0;
            reds[(wq * 16 + g + 8) * 2 + wk] = sum1;
        }

        // ---- pack P hi/lo into A fragments (registers) ----
        uint32_t pha[16], phb[16], pla[16], plb[16];
        #pragma unroll
        for (int i = 0; i < 16; i++) {
            const __nv_bfloat16 h0 = __float2bfloat16(s[i][0]);
            const __nv_bfloat16 h1 = __float2bfloat16(s[i][1]);
            const __nv_bfloat16 h2 = __float2bfloat16(s[i][2]);
            const __nv_bfloat16 h3 = __float2bfloat16(s[i][3]);
            __nv_bfloat162 v;
            v.x = h0; v.y = h1; pha[i] = *reinterpret_cast<uint32_t*>(&v);
            v.x = h2; v.y = h3; phb[i] = *reinterpret_cast<uint32_t*>(&v);
            pla[i] = packbf2(s[i][0] - __bfloat162float(h0), s[i][1] - __bfloat162float(h1));
            plb[i] = packbf2(s[i][2] - __bfloat162float(h2), s[i][3] - __bfloat162float(h3));
        }

        // ---- O_partial = P V over this warp's 128 keys (bf16x3) ----
        float o[8][4];
        #pragma unroll
        for (int i = 0; i < 8; i++)
            #pragma unroll
            for (int j = 0; j < 4; j++) o[i][j] = 0.f;

        #pragma unroll
        for (int kg = 0; kg < 8; kg++) {
            uint32_t afh[4] = { pha[2*kg], phb[2*kg], pha[2*kg+1], phb[2*kg+1] };
            uint32_t afl[4] = { pla[2*kg], plb[2*kg], pla[2*kg+1], plb[2*kg+1] };
            const int vrow = vrow_b + kg * 16;
            #pragma unroll
            for (int dg = 0; dg < 4; dg++) {
                uint32_t bh[4], bl[4];
                ldsm4t(bh, swza(sb + SAT_V_HI, vrow, dg * 2 + vchalf));
                ldsm4t(bl, swza(sb + SAT_V_LO, vrow, dg * 2 + vchalf));
                mma_bf16(o[2 * dg + 0], afh, bh[0], bh[1]);
                mma_bf16(o[2 * dg + 1], afh, bh[2], bh[3]);
                mma_bf16(o[2 * dg + 0], afl, bh[0], bh[1]);
                mma_bf16(o[2 * dg + 1], afl, bh[2], bh[3]);
                mma_bf16(o[2 * dg + 0], afh, bl[0], bl[1]);
                mma_bf16(o[2 * dg + 1], afh, bl[2], bl[3]);
            }
        }

        // ---- reduce the two key-halves, normalize, write hi/lo planes ----
        if (wk == 0) {
            #pragma unroll
            for (int dt = 0; dt < 8; dt++) {
                osm[(wq * 16 + g) * 68 + dt * 8 + 2 * t]         = o[dt][0];
                osm[(wq * 16 + g) * 68 + dt * 8 + 2 * t + 1]     = o[dt][1];
                osm[(wq * 16 + g + 8) * 68 + dt * 8 + 2 * t]     = o[dt][2];
                osm[(wq * 16 + g + 8) * 68 + dt * 8 + 2 * t + 1] = o[dt][3];
            }
        }
        __syncthreads();
        if (wk == 1) {
            #pragma unroll
            for (int dt = 0; dt < 8; dt++) {
                osm[(wq * 16 + g) * 68 + dt * 8 + 2 * t]         += o[dt][0];
                osm[(wq * 16 + g) * 68 + dt * 8 + 2 * t + 1]     += o[dt][1];
                osm[(wq * 16 + g + 8) * 68 + dt * 8 + 2 * t]     += o[dt][2];
                osm[(wq * 16 + g + 8) * 68 + dt * 8 + 2 * t + 1] += o[dt][3];
            }
        }
        __syncthreads();
        {
            const int row = tid >> 2;
            const int d0 = (tid & 3) * 16;
            const float inv = 1.f / (reds[row * 2] + reds[row * 2 + 1]);
            const size_t ob = (tokbase + ch * 64 + row) * DMODEL + h * DH + d0;
            union { uint4 u[2]; __nv_bfloat16 b[16]; } hb, lb;
            #pragma unroll
            for (int j = 0; j < 16; j++) {
                const float v = osm[row * 68 + d0 + j] * inv;
                hb.b[j] = __float2bfloat16(v);
                lb.b[j] = __float2bfloat16(v - __bfloat162float(hb.b[j]));
            }
            *(uint4*)(athi + ob)     = hb.u[0];
            *(uint4*)(athi + ob + 8) = hb.u[1];
            *(uint4*)(atlo + ob)     = lb.u[0];
            *(uint4*)(atlo + ob + 8) = lb.u[1];
        }
        __syncthreads();
        if (ch < 3) {
            loadQ(ch + 1);
            CP_COMMIT(); CP_WAIT(0);
            __syncthreads();
        }
    }
}

// ---------------- temporal attention (fp32 compute, plane IO) -------------
__global__ __launch_bounds__(128) void temporal_attn_kernel(
    const __nv_bfloat16* __restrict__ qhi, const __nv_bfloat16* __restrict__ qlo,
    __nv_bfloat16* __restrict__ athi, __nv_bfloat16* __restrict__ atlo)
{
    __shared__ float Qs[16][64], Ks2[16][64], Vs[16][64];
    __shared__ float Ss[16][17];

    const int tid = threadIdx.x;
    const int h  = blockIdx.x & 7;
    const int ns = blockIdx.x >> 3;
    const int s  = ns & 255;
    const int n  = ns >> 8;
    const int qoff = 512  + h * DH;
    const int koff = 1536 + h * DH;
    const int voff = 2560 + h * DH;

    {
        const int r  = tid >> 3;
        const int dg = (tid & 7) * 8;
        const size_t tok = ((size_t)(n * 16 + r) * 256 + s) * QKVD;
        #pragma unroll
        for (int a = 0; a < 3; a++) {
            const int off = (a == 0) ? qoff : (a == 1) ? koff : voff;
            uint4 hv = *(const uint4*)(qhi + tok + off + dg);
            uint4 lv = *(const uint4*)(qlo + tok + off + dg);
            const __nv_bfloat16* hp = reinterpret_cast<const __nv_bfloat16*>(&hv);
            const __nv_bfloat16* lp = reinterpret_cast<const __nv_bfloat16*>(&lv);
            float* dst = (a == 0) ? &Qs[r][dg] : (a == 1) ? &Ks2[r][dg] : &Vs[r][dg];
            #pragma unroll
            for (int j = 0; j < 8; j++)
                dst[j] = __bfloat162float(hp[j]) + __bfloat162float(lp[j]);
        }
    }
    __syncthreads();

    {
        const int q = tid >> 3;
        const int k = tid & 7;
        float s0 = 0.f, s1 = 0.f;
        #pragma unroll 16
        for (int d = 0; d < 64; d++) {
            const float qv = Qs[q][d];
            s0 = fmaf(qv, Ks2[k][d], s0);
            s1 = fmaf(qv, Ks2[k + 8][d], s1);
        }
        Ss[q][k]     = s0 * SCALE;
        Ss[q][k + 8] = s1 * SCALE;
    }
    __syncthreads();

    if (tid < 16) {
        float m = -1e30f;
        #pragma unroll
        for (int k = 0; k < 16; k++) m = fmaxf(m, Ss[tid][k]);
        float sum = 0.f;
        #pragma unroll
        for (int k = 0; k < 16; k++) {
            const float e = __expf(Ss[tid][k] - m);
            Ss[tid][k] = e;
            sum += e;
        }
        const float inv = 1.f / sum;
        #pragma unroll
        for (int k = 0; k < 16; k++) Ss[tid][k] *= inv;
    }
    __syncthreads();

    {
        const int q  = tid >> 3;
        const int dg = (tid & 7) * 8;
        float o[8];
        #pragma unroll
        for (int j = 0; j < 8; j++) o[j] = 0.f;
        #pragma unroll
        for (int k = 0; k < 16; k++) {
            const float p = Ss[q][k];
            #pragma unroll
            for (int j = 0; j < 8; j++) o[j] = fmaf(p, Vs[k][dg + j], o[j]);
        }
        const size_t row = (size_t)(n * 16 + q) * 256 + s;
        const size_t ob = row * DMODEL + 512 + h * DH + dg;
        union { uint4 u; __nv_bfloat16 b[8]; } hb, lb;
        #pragma unroll
        for (int j = 0; j < 8; j++) {
            hb.b[j] = __float2bfloat16(o[j]);
            lb.b[j] = __float2bfloat16(o[j] - __bfloat162float(hb.b[j]));
        }
        *(uint4*)(athi + ob) = hb.u;
        *(uint4*)(atlo + ob) = lb.u;
    }
}

// ---------------- launch ----------------
extern "C" void kernel_launch(void* const* d_in, const int* in_sizes, int n_in,
                              void* d_out, int out_size)
{
    const float* x     = (const float*)d_in[0];
    const float* Wqkv  = (const float*)d_in[1];
    const float* Wproj = (const float*)d_in[2];
    const float* bproj = (const float*)d_in[3];
    float* out = (float*)d_out;

    __nv_bfloat16 *qkvhi, *qkvlo, *atthi, *attlo, *acthi, *actlo;
    __nv_bfloat16 *wqhi, *wqlo, *wphi, *wplo;
    cudaGetSymbolAddress((void**)&qkvhi, g_qkvhi);
    cudaGetSymbolAddress((void**)&qkvlo, g_qkvlo);
    cudaGetSymbolAddress((void**)&atthi, g_atthi);
    cudaGetSymbolAddress((void**)&attlo, g_attlo);
    cudaGetSymbolAddress((void**)&acthi, g_acthi);
    cudaGetSymbolAddress((void**)&actlo, g_actlo);
    cudaGetSymbolAddress((void**)&wqhi, g_wqhi);
    cudaGetSymbolAddress((void**)&wqlo, g_wqlo);
    cudaGetSymbolAddress((void**)&wphi, g_wphi);
    cudaGetSymbolAddress((void**)&wplo, g_wplo);

    cudaFuncSetAttribute(gemm_mma_kernel,
                         cudaFuncAttributeMaxDynamicSharedMemorySize, GEMM_SMEM);
    cudaFuncSetAttribute(spatial_attn_mma,
                         cudaFuncAttributeMaxDynamicSharedMemorySize, SAT_SMEM);

    // 1) splits
    split_act_kernel<<<NTOK * DMODEL / 256, 256>>>(x, acthi, actlo);
    split_w_kernel<<<dim3(QKVD / 32, DMODEL / 32), 256>>>(Wqkv, wqhi, wqlo, QKVD);
    split_w_kernel<<<dim3(DMODEL / 32, DMODEL / 32), 256>>>(Wproj, wphi, wplo, DMODEL);

    // 2) QKV GEMM -> bf16 hi/lo planes
    gemm_mma_kernel<<<dim3(QKVD / BN, NTOK / BM), 256, GEMM_SMEM>>>(
        acthi, actlo, wqhi, wqlo, nullptr, nullptr, qkvhi, qkvlo, NTOK, QKVD);

    // 3) attention -> att hi/lo planes
    spatial_attn_mma<<<256, 256, SAT_SMEM>>>(qkvhi, qkvlo, atthi, attlo);
    temporal_attn_kernel<<<4096, 128>>>(qkvhi, qkvlo, atthi, attlo);

    // 4) proj GEMM (fp32 out + bias)
    gemm_mma_kernel<<<dim3(DMODEL / BN, NTOK / BM), 256, GEMM_SMEM>>>(
        atthi, attlo, wphi, wplo, bproj, out, nullptr, nullptr, NTOK, DMODEL);
}